// round 3
// baseline (speedup 1.0000x reference)
#include <cuda_runtime.h>
#include <cstdint>

#define BB 16384
#define EE 64
#define DD 128
#define ES 3
#define NBLK (BB / 64)          // 256 k1 blocks

typedef unsigned long long ull;

// ---------------- device scratch (static; no allocations allowed) -------------
__device__ int    g_offsets[EE + 1];
__device__ int    g_ntiles;
__device__ int    g_picked[BB * ES];
__device__ int    g_loc[BB * ES];
__device__ float  g_w[BB * ES];
__device__ int    g_entry_token[BB * ES];
__device__ int    g_pos[BB * ES];
__device__ int2   g_tiles[1024];
__device__ int    g_blockhist[NBLK * EE];   // per-k1-block expert histogram
__device__ int    g_blockbase[NBLK * EE];   // global scatter base per (block, expert)
__device__ float  g_scratch[(size_t)BB * ES * DD];   // 25 MB (y + bias rows)

// ---------------- packed f32x2 helpers ---------------------------------------
__device__ __forceinline__ ull pack2(float lo, float hi) {
    ull r;
    asm("mov.b64 %0, {%1, %2};" : "=l"(r) : "f"(lo), "f"(hi));
    return r;
}
__device__ __forceinline__ float2 unpack2(ull v) {
    float2 f;
    asm("mov.b64 {%0, %1}, %2;" : "=f"(f.x), "=f"(f.y) : "l"(v));
    return f;
}
__device__ __forceinline__ ull fma2(ull a, ull b, ull c) {
    ull d;
    asm("fma.rn.f32x2 %0, %1, %2, %3;" : "=l"(d) : "l"(a), "l"(b), "l"(c));
    return d;
}
__device__ __forceinline__ ull add2(ull a, ull b) {
    ull d;
    asm("add.rn.f32x2 %0, %1, %2;" : "=l"(d) : "l"(a), "l"(b));
    return d;
}

// ---------------- K1: accurate routing (no global atomics) --------------------
// d_e = s^2/128 * (|x|^2 + |c_e|^2 -+ 2 x.c_e); dots fp32 split-acc, rest fp64.
#define K1_XP 68
#define K1_CP 36
#define K1_TP 36
#define K1_SMEM ((128 * K1_XP + 128 * K1_CP + 64 * K1_TP + 64 + 64) * 4)

__global__ __launch_bounds__(256) void k1_route(const float* __restrict__ x,
                                                const float* __restrict__ dscale,
                                                const float* __restrict__ cent) {
    extern __shared__ float sm[];
    float*  xs   = sm;                         // [128][K1_XP]  x^T (k-major)
    float*  cs   = xs + 128 * K1_XP;           // [128][K1_CP]  c^T, experts 0..31
    float*  ts   = cs + 128 * K1_CP;           // [64][K1_TP]   dot results
    double* nc2s = (double*)(ts + 64 * K1_TP); // [32]
    int*    hist = (int*)(nc2s + 32);          // [64]

    int tid = threadIdx.x;
    if (tid < 64) hist[tid] = 0;
    int t0 = blockIdx.x * 64;

    // load x tile transposed
    const float4* x4 = (const float4*)x;
#pragma unroll
    for (int i = 0; i < 8; i++) {
        int f = i * 256 + tid;
        int tr = f & 63, kc = f >> 6;
        float4 v = __ldg(x4 + (size_t)(t0 + tr) * 32 + kc);
        xs[(kc * 4 + 0) * K1_XP + tr] = v.x;
        xs[(kc * 4 + 1) * K1_XP + tr] = v.y;
        xs[(kc * 4 + 2) * K1_XP + tr] = v.z;
        xs[(kc * 4 + 3) * K1_XP + tr] = v.w;
    }
    // load centroids 0..31 transposed
    const float4* c4 = (const float4*)cent;
#pragma unroll
    for (int i = 0; i < 4; i++) {
        int f = i * 256 + tid;
        int er = f & 31, kc = f >> 5;
        float4 v = __ldg(c4 + (size_t)er * 32 + kc);
        cs[(kc * 4 + 0) * K1_CP + er] = v.x;
        cs[(kc * 4 + 1) * K1_CP + er] = v.y;
        cs[(kc * 4 + 2) * K1_CP + er] = v.z;
        cs[(kc * 4 + 3) * K1_CP + er] = v.w;
    }
    __syncthreads();

    // warp 0: centroid norms in fp64 (overlapped with dot compute of other warps)
    if (tid < 32) {
        double a0 = 0.0, a1 = 0.0;
#pragma unroll 8
        for (int k = 0; k < 128; k += 2) {
            double u0 = (double)cs[(k + 0) * K1_CP + tid]; a0 = fma(u0, u0, a0);
            double u1 = (double)cs[(k + 1) * K1_CP + tid]; a1 = fma(u1, u1, a1);
        }
        nc2s[tid] = a0 + a1;
    }

    // dots: each thread = 2 tokens x 4 experts, 4-way k-split accumulators
    {
        int tx = tid & 7, ty = tid >> 3;
        ull acc[2][2][4];
#pragma unroll
        for (int i = 0; i < 2; i++)
#pragma unroll
            for (int j = 0; j < 2; j++)
#pragma unroll
                for (int s = 0; s < 4; s++) acc[i][j][s] = 0ULL;

        const float* ap = xs + ty * 2;
        const float* bp = cs + tx * 4;
#pragma unroll 4
        for (int k = 0; k < 128; k += 4) {
#pragma unroll
            for (int s = 0; s < 4; s++) {
                float2  a  = *(const float2*)(ap + (k + s) * K1_XP);
                double2 nb = *(const double2*)(bp + (k + s) * K1_CP);
                ull b01 = __double_as_longlong(nb.x);
                ull b23 = __double_as_longlong(nb.y);
                ull a0 = pack2(a.x, a.x), a1 = pack2(a.y, a.y);
                acc[0][0][s] = fma2(a0, b01, acc[0][0][s]);
                acc[0][1][s] = fma2(a0, b23, acc[0][1][s]);
                acc[1][0][s] = fma2(a1, b01, acc[1][0][s]);
                acc[1][1][s] = fma2(a1, b23, acc[1][1][s]);
            }
        }
#pragma unroll
        for (int i = 0; i < 2; i++) {
            ull s01 = add2(add2(acc[i][0][0], acc[i][0][1]),
                           add2(acc[i][0][2], acc[i][0][3]));
            ull s23 = add2(add2(acc[i][1][0], acc[i][1][1]),
                           add2(acc[i][1][2], acc[i][1][3]));
            float2 v01 = unpack2(s01), v23 = unpack2(s23);
            int tok = ty * 2 + i;
            *(float4*)(ts + tok * K1_TP + tx * 4) =
                make_float4(v01.x, v01.y, v23.x, v23.y);
        }
    }
    __syncthreads();

    // per-token: |x|^2 (fp64), 64 distances (fp64), top-3, weights, local ranks
    if (tid < 64) {
        int tok = tid;
        double a0 = 0.0, a1 = 0.0, a2 = 0.0, a3 = 0.0;
#pragma unroll 8
        for (int k = 0; k < 128; k += 4) {
            double u0 = (double)xs[(k + 0) * K1_XP + tok]; a0 = fma(u0, u0, a0);
            double u1 = (double)xs[(k + 1) * K1_XP + tok]; a1 = fma(u1, u1, a1);
            double u2 = (double)xs[(k + 2) * K1_XP + tok]; a2 = fma(u2, u2, a2);
            double u3 = (double)xs[(k + 3) * K1_XP + tok]; a3 = fma(u3, u3, a3);
        }
        double nx2 = (a0 + a1) + (a2 + a3);

        float  s  = __ldg(dscale);
        double Kd = ((double)s * (double)s) * (1.0 / 128.0);

        double v0 = 1e300, v1 = 1e300, v2 = 1e300;
        int    i0 = 0, i1 = 0, i2 = 0;
        for (int e = 0; e < 64; e++) {
            int    ei = e & 31;
            double t  = (double)ts[tok * K1_TP + ei];
            double br = nx2 + nc2s[ei];
            double dd = Kd * (e < 32 ? fma(-2.0, t, br) : fma(2.0, t, br));
            if (dd < v0)      { v2 = v1; i2 = i1; v1 = v0; i1 = i0; v0 = dd; i0 = e; }
            else if (dd < v1) { v2 = v1; i2 = i1; v1 = dd; i1 = e; }
            else if (dd < v2) { v2 = dd; i2 = e; }
        }
        // weights from distances to experts 0,1,2 (reference quirk)
        float d0 = (float)(Kd * fma(-2.0, (double)ts[tok * K1_TP + 0], nx2 + nc2s[0]));
        float d1 = (float)(Kd * fma(-2.0, (double)ts[tok * K1_TP + 1], nx2 + nc2s[1]));
        float d2 = (float)(Kd * fma(-2.0, (double)ts[tok * K1_TP + 2], nx2 + nc2s[2]));
        float w0 = 1.0f / (1.0f + d0);
        float w1 = 1.0f / (1.0f + d1);
        float w2 = 1.0f / (1.0f + d2);
        float z  = w0 + w1 + w2;
        int b = t0 + tok;
        g_picked[b * 3 + 0] = i0; g_picked[b * 3 + 1] = i1; g_picked[b * 3 + 2] = i2;
        g_w[b * 3 + 0] = w0 / z; g_w[b * 3 + 1] = w1 / z; g_w[b * 3 + 2] = w2 / z;
        g_loc[b * 3 + 0] = atomicAdd(&hist[i0], 1);
        g_loc[b * 3 + 1] = atomicAdd(&hist[i1], 1);
        g_loc[b * 3 + 2] = atomicAdd(&hist[i2], 1);
    }
    __syncthreads();
    if (tid < 64) g_blockhist[blockIdx.x * 64 + tid] = hist[tid];
}

// ---------------- K2: scan over (block, expert) histograms --------------------
// 256 threads: expert e = tid&63, chunk c = tid>>6 (4 chunks x 64 blocks).
__global__ __launch_bounds__(256) void k2_scan() {
    __shared__ int csum[4 * 64];
    __shared__ int cnts[64];
    __shared__ int off[65];
    __shared__ int toff[64];
    int tid = threadIdx.x;
    int e = tid & 63, c = tid >> 6;

    int s = 0;
#pragma unroll 8
    for (int i = 0; i < 64; i++) s += g_blockhist[((c << 6) + i) * 64 + e];
    csum[c * 64 + e] = s;
    __syncthreads();

    if (tid < 64) {
        int t0 = csum[0 * 64 + tid], t1 = csum[1 * 64 + tid];
        int t2 = csum[2 * 64 + tid], t3 = csum[3 * 64 + tid];
        cnts[tid] = t0 + t1 + t2 + t3;
        csum[0 * 64 + tid] = 0;
        csum[1 * 64 + tid] = t0;
        csum[2 * 64 + tid] = t0 + t1;
        csum[3 * 64 + tid] = t0 + t1 + t2;
    }
    __syncthreads();

    if (tid == 0) {
        int o = 0, to = 0;
        for (int i = 0; i < 64; i++) {
            off[i] = o; toff[i] = to;
            o += cnts[i]; to += (cnts[i] + 127) >> 7;
        }
        off[64] = o; g_ntiles = to;
    }
    __syncthreads();

    if (tid < 64) {
        g_offsets[tid] = off[tid];
        int nt = (cnts[tid] + 127) >> 7;
        for (int i = 0; i < nt; i++)
            g_tiles[toff[tid] + i] = make_int2(tid, off[tid] + (i << 7));
    }
    if (tid == 0) g_offsets[64] = off[64];
    __syncthreads();

    // pass 2: per-(block, expert) global base (includes expert offset)
    int run = off[e] + csum[c * 64 + e];
    for (int i = 0; i < 64; i++) {
        int idx = ((c << 6) + i) * 64 + e;
        int v = g_blockhist[idx];
        g_blockbase[idx] = run;
        run += v;
    }
}

// ---------------- K3: scatter (no atomics, pure address math) ------------------
__global__ __launch_bounds__(256) void k3_scatter() {
    int b = blockIdx.x * 256 + threadIdx.x;
    int blk = b >> 6;
#pragma unroll
    for (int j = 0; j < 3; j++) {
        int e = g_picked[b * 3 + j];
        int p = g_blockbase[blk * 64 + e] + g_loc[b * 3 + j];
        g_entry_token[p] = b;
        g_pos[b * 3 + j] = p;
    }
}

// ---------------- K4: grouped GEMM, 128 tokens x 128 outs, 8x8/thread ---------
#define K4_SMEM ((128 * 128 + 128 * 128 + 128) * 4)

__global__ __launch_bounds__(256) void k4_gemm(const float* __restrict__ x,
                                               const float* __restrict__ W,
                                               const float* __restrict__ bias) {
    int t = blockIdx.x;
    if (t >= g_ntiles) return;
    int2 tl = g_tiles[t];
    int e = tl.x, rs = tl.y;
    int rows = g_offsets[e + 1] - rs;
    if (rows > 128) rows = 128;

    extern __shared__ float sm[];
    float* ws = sm;                 // [128][128] W_e (k-major)
    float* as = ws + 128 * 128;     // [128][128] gathered x^T: as[k][tok]
    float* bs = as + 128 * 128;     // [128] bias_e

    int tid = threadIdx.x;
    const float4* w4 = (const float4*)(W + (size_t)e * DD * DD);
    float4* ws4 = (float4*)ws;
#pragma unroll
    for (int i = 0; i < 16; i++) ws4[i * 256 + tid] = __ldg(w4 + i * 256 + tid);
    if (tid < 32) ((float4*)bs)[tid] = __ldg((const float4*)(bias + (size_t)e * DD) + tid);

    const float4* x4 = (const float4*)x;
#pragma unroll
    for (int i = 0; i < 16; i++) {
        int f = i * 256 + tid;
        int tr = f & 127, kc = f >> 7;
        float4 v = make_float4(0.f, 0.f, 0.f, 0.f);
        if (tr < rows) {
            int tok = g_entry_token[rs + tr];
            v = __ldg(x4 + (size_t)tok * 32 + kc);
        }
        as[(kc * 4 + 0) * 128 + tr] = v.x;
        as[(kc * 4 + 1) * 128 + tr] = v.y;
        as[(kc * 4 + 2) * 128 + tr] = v.z;
        as[(kc * 4 + 3) * 128 + tr] = v.w;
    }
    __syncthreads();

    int tx = tid & 15, ty = tid >> 4;   // tx: 8 outs at tx*8; ty: 8 tokens at ty*8
    ull acc[8][4];
#pragma unroll
    for (int i = 0; i < 8; i++)
#pragma unroll
        for (int j = 0; j < 4; j++) acc[i][j] = 0ULL;

    const float* ap = as + ty * 8;
    const float* bp = ws + tx * 8;
#pragma unroll 2
    for (int k = 0; k < 128; k++) {
        float4  al = *(const float4*)(ap + k * 128);
        float4  ah = *(const float4*)(ap + k * 128 + 4);
        double2 bl = *(const double2*)(bp + k * 128);
        double2 bh = *(const double2*)(bp + k * 128 + 4);
        ull b0 = __double_as_longlong(bl.x);
        ull b1 = __double_as_longlong(bl.y);
        ull b2 = __double_as_longlong(bh.x);
        ull b3 = __double_as_longlong(bh.y);
        ull a0 = pack2(al.x, al.x), a1 = pack2(al.y, al.y);
        ull a2 = pack2(al.z, al.z), a3 = pack2(al.w, al.w);
        ull a4 = pack2(ah.x, ah.x), a5 = pack2(ah.y, ah.y);
        ull a6 = pack2(ah.z, ah.z), a7 = pack2(ah.w, ah.w);
        acc[0][0] = fma2(a0, b0, acc[0][0]); acc[0][1] = fma2(a0, b1, acc[0][1]);
        acc[0][2] = fma2(a0, b2, acc[0][2]); acc[0][3] = fma2(a0, b3, acc[0][3]);
        acc[1][0] = fma2(a1, b0, acc[1][0]); acc[1][1] = fma2(a1, b1, acc[1][1]);
        acc[1][2] = fma2(a1, b2, acc[1][2]); acc[1][3] = fma2(a1, b3, acc[1][3]);
        acc[2][0] = fma2(a2, b0, acc[2][0]); acc[2][1] = fma2(a2, b1, acc[2][1]);
        acc[2][2] = fma2(a2, b2, acc[2][2]); acc[2][3] = fma2(a2, b3, acc[2][3]);
        acc[3][0] = fma2(a3, b0, acc[3][0]); acc[3][1] = fma2(a3, b1, acc[3][1]);
        acc[3][2] = fma2(a3, b2, acc[3][2]); acc[3][3] = fma2(a3, b3, acc[3][3]);
        acc[4][0] = fma2(a4, b0, acc[4][0]); acc[4][1] = fma2(a4, b1, acc[4][1]);
        acc[4][2] = fma2(a4, b2, acc[4][2]); acc[4][3] = fma2(a4, b3, acc[4][3]);
        acc[5][0] = fma2(a5, b0, acc[5][0]); acc[5][1] = fma2(a5, b1, acc[5][1]);
        acc[5][2] = fma2(a5, b2, acc[5][2]); acc[5][3] = fma2(a5, b3, acc[5][3]);
        acc[6][0] = fma2(a6, b0, acc[6][0]); acc[6][1] = fma2(a6, b1, acc[6][1]);
        acc[6][2] = fma2(a6, b2, acc[6][2]); acc[6][3] = fma2(a6, b3, acc[6][3]);
        acc[7][0] = fma2(a7, b0, acc[7][0]); acc[7][1] = fma2(a7, b1, acc[7][1]);
        acc[7][2] = fma2(a7, b2, acc[7][2]); acc[7][3] = fma2(a7, b3, acc[7][3]);
    }

    float4 bv0 = *(const float4*)(bs + tx * 8);
    float4 bv1 = *(const float4*)(bs + tx * 8 + 4);
#pragma unroll
    for (int i = 0; i < 8; i++) {
        int tr = ty * 8 + i;
        if (tr < rows) {
            float* o = g_scratch + (size_t)(rs + tr) * DD;
            float2 p0 = unpack2(acc[i][0]), p1 = unpack2(acc[i][1]);
            float2 p2 = unpack2(acc[i][2]), p3 = unpack2(acc[i][3]);
            *(float4*)(o + tx * 8)     = make_float4(p0.x + bv0.x, p0.y + bv0.y,
                                                     p1.x + bv0.z, p1.y + bv0.w);
            *(float4*)(o + tx * 8 + 4) = make_float4(p2.x + bv1.x, p2.y + bv1.y,
                                                     p3.x + bv1.z, p3.y + bv1.w);
        }
    }
}

// ---------------- K5: weighted combine ----------------------------------------
__global__ __launch_bounds__(256) void k5_combine(float* __restrict__ out) {
    int idx = blockIdx.x * 256 + threadIdx.x;
    int b = idx >> 5;
    int c = (idx & 31) * 4;
    float4 r = make_float4(0.f, 0.f, 0.f, 0.f);
#pragma unroll
    for (int j = 0; j < 3; j++) {
        float w = g_w[b * 3 + j];
        int   p = g_pos[b * 3 + j];
        float4 sv = *(const float4*)(g_scratch + (size_t)p * DD + c);
        r.x += w * sv.x;
        r.y += w * sv.y;
        r.z += w * sv.z;
        r.w += w * sv.w;
    }
    *(float4*)(out + (size_t)b * DD + c) = r;
}

// ---------------- launch ------------------------------------------------------
extern "C" void kernel_launch(void* const* d_in, const int* in_sizes, int n_in,
                              void* d_out, int out_size) {
    const float* x    = (const float*)d_in[0];
    const float* dsc  = (const float*)d_in[1];
    const float* cent = (const float*)d_in[2];
    const float* W    = (const float*)d_in[3];
    const float* bias = (const float*)d_in[4];
    float* out = (float*)d_out;

    cudaFuncSetAttribute(k1_route, cudaFuncAttributeMaxDynamicSharedMemorySize, K1_SMEM);
    cudaFuncSetAttribute(k4_gemm,  cudaFuncAttributeMaxDynamicSharedMemorySize, K4_SMEM);

    k1_route<<<NBLK, 256, K1_SMEM>>>(x, dsc, cent);
    k2_scan<<<1, 256>>>();
    k3_scatter<<<BB / 256, 256>>>();
    k4_gemm<<<448, 256, K4_SMEM>>>(x, W, bias);   // 448 >= max tile count
    k5_combine<<<BB * 32 / 256, 256>>>(out);
}

// round 4
// speedup vs baseline: 1.0321x; 1.0321x over previous
#include <cuda_runtime.h>
#include <cstdint>

#define BB 16384
#define EE 64
#define DD 128
#define ES 3
#define NBLK (BB / 64)          // 256 k1 blocks

typedef unsigned long long ull;

// ---------------- device scratch (static; no allocations allowed) -------------
__device__ int    g_offsets[EE + 1];
__device__ int    g_ntiles;
__device__ int    g_picked[BB * ES];
__device__ int    g_loc[BB * ES];
__device__ float  g_w[BB * ES];
__device__ int    g_entry_token[BB * ES];
__device__ int    g_pos[BB * ES];
__device__ int2   g_tiles[1024];
__device__ int    g_blockhist[NBLK * EE];   // per-k1-block expert histogram
__device__ int    g_blockbase[NBLK * EE];   // global scatter base per (block, expert)
__device__ float  g_scratch[(size_t)BB * ES * DD];   // 25 MB (y + bias rows)

// ---------------- packed f32x2 helpers ---------------------------------------
__device__ __forceinline__ ull pack2(float lo, float hi) {
    ull r;
    asm("mov.b64 %0, {%1, %2};" : "=l"(r) : "f"(lo), "f"(hi));
    return r;
}
__device__ __forceinline__ float2 unpack2(ull v) {
    float2 f;
    asm("mov.b64 {%0, %1}, %2;" : "=f"(f.x), "=f"(f.y) : "l"(v));
    return f;
}
__device__ __forceinline__ ull fma2(ull a, ull b, ull c) {
    ull d;
    asm("fma.rn.f32x2 %0, %1, %2, %3;" : "=l"(d) : "l"(a), "l"(b), "l"(c));
    return d;
}
__device__ __forceinline__ ull add2(ull a, ull b) {
    ull d;
    asm("add.rn.f32x2 %0, %1, %2;" : "=l"(d) : "l"(a), "l"(b));
    return d;
}

// ---------------- K1: accurate routing (no global atomics) --------------------
// d_e = s^2/128 * (|x|^2 + |c_e|^2 -+ 2 x.c_e); dots fp32 split-acc, rest fp64.
#define K1_XP 68
#define K1_CP 36
#define K1_TP 36
#define K1_SMEM ((128 * K1_XP + 128 * K1_CP + 64 * K1_TP + 64 + 64) * 4)

__global__ __launch_bounds__(256) void k1_route(const float* __restrict__ x,
                                                const float* __restrict__ dscale,
                                                const float* __restrict__ cent) {
    extern __shared__ float sm[];
    float*  xs   = sm;                         // [128][K1_XP]  x^T (k-major)
    float*  cs   = xs + 128 * K1_XP;           // [128][K1_CP]  c^T, experts 0..31
    float*  ts   = cs + 128 * K1_CP;           // [64][K1_TP]   dot results
    double* nc2s = (double*)(ts + 64 * K1_TP); // [32]
    int*    hist = (int*)(nc2s + 32);          // [64]

    int tid = threadIdx.x;
    if (tid < 64) hist[tid] = 0;
    int t0 = blockIdx.x * 64;

    // load x tile transposed
    const float4* x4 = (const float4*)x;
#pragma unroll
    for (int i = 0; i < 8; i++) {
        int f = i * 256 + tid;
        int tr = f & 63, kc = f >> 6;
        float4 v = __ldg(x4 + (size_t)(t0 + tr) * 32 + kc);
        xs[(kc * 4 + 0) * K1_XP + tr] = v.x;
        xs[(kc * 4 + 1) * K1_XP + tr] = v.y;
        xs[(kc * 4 + 2) * K1_XP + tr] = v.z;
        xs[(kc * 4 + 3) * K1_XP + tr] = v.w;
    }
    // load centroids 0..31 transposed
    const float4* c4 = (const float4*)cent;
#pragma unroll
    for (int i = 0; i < 4; i++) {
        int f = i * 256 + tid;
        int er = f & 31, kc = f >> 5;
        float4 v = __ldg(c4 + (size_t)er * 32 + kc);
        cs[(kc * 4 + 0) * K1_CP + er] = v.x;
        cs[(kc * 4 + 1) * K1_CP + er] = v.y;
        cs[(kc * 4 + 2) * K1_CP + er] = v.z;
        cs[(kc * 4 + 3) * K1_CP + er] = v.w;
    }
    __syncthreads();

    // warp 0: centroid norms in fp64 (overlapped with dot compute of other warps)
    if (tid < 32) {
        double a0 = 0.0, a1 = 0.0;
#pragma unroll 8
        for (int k = 0; k < 128; k += 2) {
            double u0 = (double)cs[(k + 0) * K1_CP + tid]; a0 = fma(u0, u0, a0);
            double u1 = (double)cs[(k + 1) * K1_CP + tid]; a1 = fma(u1, u1, a1);
        }
        nc2s[tid] = a0 + a1;
    }

    // dots: each thread = 2 tokens x 4 experts, 4-way k-split accumulators
    {
        int tx = tid & 7, ty = tid >> 3;
        ull acc[2][2][4];
#pragma unroll
        for (int i = 0; i < 2; i++)
#pragma unroll
            for (int j = 0; j < 2; j++)
#pragma unroll
                for (int s = 0; s < 4; s++) acc[i][j][s] = 0ULL;

        const float* ap = xs + ty * 2;
        const float* bp = cs + tx * 4;
#pragma unroll 4
        for (int k = 0; k < 128; k += 4) {
#pragma unroll
            for (int s = 0; s < 4; s++) {
                float2  a  = *(const float2*)(ap + (k + s) * K1_XP);
                double2 nb = *(const double2*)(bp + (k + s) * K1_CP);
                ull b01 = __double_as_longlong(nb.x);
                ull b23 = __double_as_longlong(nb.y);
                ull a0 = pack2(a.x, a.x), a1 = pack2(a.y, a.y);
                acc[0][0][s] = fma2(a0, b01, acc[0][0][s]);
                acc[0][1][s] = fma2(a0, b23, acc[0][1][s]);
                acc[1][0][s] = fma2(a1, b01, acc[1][0][s]);
                acc[1][1][s] = fma2(a1, b23, acc[1][1][s]);
            }
        }
#pragma unroll
        for (int i = 0; i < 2; i++) {
            ull s01 = add2(add2(acc[i][0][0], acc[i][0][1]),
                           add2(acc[i][0][2], acc[i][0][3]));
            ull s23 = add2(add2(acc[i][1][0], acc[i][1][1]),
                           add2(acc[i][1][2], acc[i][1][3]));
            float2 v01 = unpack2(s01), v23 = unpack2(s23);
            int tok = ty * 2 + i;
            *(float4*)(ts + tok * K1_TP + tx * 4) =
                make_float4(v01.x, v01.y, v23.x, v23.y);
        }
    }
    __syncthreads();

    // per-token: |x|^2 (fp64), 64 distances (fp64), top-3, weights, local ranks
    if (tid < 64) {
        int tok = tid;
        double a0 = 0.0, a1 = 0.0, a2 = 0.0, a3 = 0.0;
#pragma unroll 8
        for (int k = 0; k < 128; k += 4) {
            double u0 = (double)xs[(k + 0) * K1_XP + tok]; a0 = fma(u0, u0, a0);
            double u1 = (double)xs[(k + 1) * K1_XP + tok]; a1 = fma(u1, u1, a1);
            double u2 = (double)xs[(k + 2) * K1_XP + tok]; a2 = fma(u2, u2, a2);
            double u3 = (double)xs[(k + 3) * K1_XP + tok]; a3 = fma(u3, u3, a3);
        }
        double nx2 = (a0 + a1) + (a2 + a3);

        float  s  = __ldg(dscale);
        double Kd = ((double)s * (double)s) * (1.0 / 128.0);

        double v0 = 1e300, v1 = 1e300, v2 = 1e300;
        int    i0 = 0, i1 = 0, i2 = 0;
        for (int e = 0; e < 64; e++) {
            int    ei = e & 31;
            double t  = (double)ts[tok * K1_TP + ei];
            double br = nx2 + nc2s[ei];
            double dd = Kd * (e < 32 ? fma(-2.0, t, br) : fma(2.0, t, br));
            if (dd < v0)      { v2 = v1; i2 = i1; v1 = v0; i1 = i0; v0 = dd; i0 = e; }
            else if (dd < v1) { v2 = v1; i2 = i1; v1 = dd; i1 = e; }
            else if (dd < v2) { v2 = dd; i2 = e; }
        }
        // weights from distances to experts 0,1,2 (reference quirk)
        float d0 = (float)(Kd * fma(-2.0, (double)ts[tok * K1_TP + 0], nx2 + nc2s[0]));
        float d1 = (float)(Kd * fma(-2.0, (double)ts[tok * K1_TP + 1], nx2 + nc2s[1]));
        float d2 = (float)(Kd * fma(-2.0, (double)ts[tok * K1_TP + 2], nx2 + nc2s[2]));
        float w0 = 1.0f / (1.0f + d0);
        float w1 = 1.0f / (1.0f + d1);
        float w2 = 1.0f / (1.0f + d2);
        float z  = w0 + w1 + w2;
        int b = t0 + tok;
        g_picked[b * 3 + 0] = i0; g_picked[b * 3 + 1] = i1; g_picked[b * 3 + 2] = i2;
        g_w[b * 3 + 0] = w0 / z; g_w[b * 3 + 1] = w1 / z; g_w[b * 3 + 2] = w2 / z;
        g_loc[b * 3 + 0] = atomicAdd(&hist[i0], 1);
        g_loc[b * 3 + 1] = atomicAdd(&hist[i1], 1);
        g_loc[b * 3 + 2] = atomicAdd(&hist[i2], 1);
    }
    __syncthreads();
    if (tid < 64) g_blockhist[blockIdx.x * 64 + tid] = hist[tid];
}

// ---------------- K2: scan over (block, expert) histograms --------------------
__global__ __launch_bounds__(256) void k2_scan() {
    __shared__ int csum[4 * 64];
    __shared__ int cnts[64];
    __shared__ int off[65];
    __shared__ int toff[64];
    int tid = threadIdx.x;
    int e = tid & 63, c = tid >> 6;

    int s = 0;
#pragma unroll 8
    for (int i = 0; i < 64; i++) s += g_blockhist[((c << 6) + i) * 64 + e];
    csum[c * 64 + e] = s;
    __syncthreads();

    if (tid < 64) {
        int t0 = csum[0 * 64 + tid], t1 = csum[1 * 64 + tid];
        int t2 = csum[2 * 64 + tid], t3 = csum[3 * 64 + tid];
        cnts[tid] = t0 + t1 + t2 + t3;
        csum[0 * 64 + tid] = 0;
        csum[1 * 64 + tid] = t0;
        csum[2 * 64 + tid] = t0 + t1;
        csum[3 * 64 + tid] = t0 + t1 + t2;
    }
    __syncthreads();

    if (tid == 0) {
        int o = 0, to = 0;
        for (int i = 0; i < 64; i++) {
            off[i] = o; toff[i] = to;
            o += cnts[i]; to += (cnts[i] + 127) >> 7;
        }
        off[64] = o; g_ntiles = to;
    }
    __syncthreads();

    if (tid < 64) {
        g_offsets[tid] = off[tid];
        int nt = (cnts[tid] + 127) >> 7;
        for (int i = 0; i < nt; i++)
            g_tiles[toff[tid] + i] = make_int2(tid, off[tid] + (i << 7));
    }
    if (tid == 0) g_offsets[64] = off[64];
    __syncthreads();

    int run = off[e] + csum[c * 64 + e];
    for (int i = 0; i < 64; i++) {
        int idx = ((c << 6) + i) * 64 + e;
        int v = g_blockhist[idx];
        g_blockbase[idx] = run;
        run += v;
    }
}

// ---------------- K3: scatter (no atomics, pure address math) ------------------
__global__ __launch_bounds__(256) void k3_scatter() {
    int b = blockIdx.x * 256 + threadIdx.x;
    int blk = b >> 6;
#pragma unroll
    for (int j = 0; j < 3; j++) {
        int e = g_picked[b * 3 + j];
        int p = g_blockbase[blk * 64 + e] + g_loc[b * 3 + j];
        g_entry_token[p] = b;
        g_pos[b * 3 + j] = p;
    }
}

// ---------------- K4: grouped GEMM, 128x128 tile, W streamed in 32-k chunks ---
// smem = as 64KB + 2x16KB wbuf + bias = 98.5KB -> 2 CTAs/SM (16 warps).
#define K4_SMEM ((128 * 128 + 2 * 32 * 128 + 128) * 4)
#define K4_GRID 296

__global__ __launch_bounds__(256, 2) void k4_gemm(const float* __restrict__ x,
                                                  const float* __restrict__ W,
                                                  const float* __restrict__ bias) {
    extern __shared__ float sm[];
    float* as = sm;                  // [128][128] gathered x^T: as[k][tok]
    float* wb = as + 128 * 128;      // [2][32][128] W chunk double buffer
    float* bs = wb + 2 * 32 * 128;   // [128] bias_e

    int tid = threadIdx.x;
    int ntiles = g_ntiles;

    for (int t = blockIdx.x; t < ntiles; t += K4_GRID) {
        int2 tl = g_tiles[t];
        int e = tl.x, rs = tl.y;
        int rows = g_offsets[e + 1] - rs;
        if (rows > 128) rows = 128;

        const float4* w4 = (const float4*)(W + (size_t)e * DD * DD);
        if (tid < 32)
            ((float4*)bs)[tid] = __ldg((const float4*)(bias + (size_t)e * DD) + tid);

        // chunk 0 direct to wbuf[0]; chunk 1 prefetched into regs
        {
            float4* d = (float4*)wb;
#pragma unroll
            for (int i = 0; i < 4; i++) d[i * 256 + tid] = __ldg(w4 + i * 256 + tid);
        }
        float4 wr[4];
#pragma unroll
        for (int i = 0; i < 4; i++) wr[i] = __ldg(w4 + 1024 + i * 256 + tid);

        // gather x rows, store transposed
        const float4* x4 = (const float4*)x;
#pragma unroll
        for (int i = 0; i < 16; i++) {
            int f = i * 256 + tid;
            int tr = f & 127, kc = f >> 7;
            float4 v = make_float4(0.f, 0.f, 0.f, 0.f);
            if (tr < rows) {
                int tok = g_entry_token[rs + tr];
                v = __ldg(x4 + (size_t)tok * 32 + kc);
            }
            as[(kc * 4 + 0) * 128 + tr] = v.x;
            as[(kc * 4 + 1) * 128 + tr] = v.y;
            as[(kc * 4 + 2) * 128 + tr] = v.z;
            as[(kc * 4 + 3) * 128 + tr] = v.w;
        }
        __syncthreads();

        int tx = tid & 15, ty = tid >> 4;
        ull acc[8][4];
#pragma unroll
        for (int i = 0; i < 8; i++)
#pragma unroll
            for (int j = 0; j < 4; j++) acc[i][j] = 0ULL;

        const float* ap = as + ty * 8;

#pragma unroll
        for (int c = 0; c < 4; c++) {
            const float* bp = wb + (c & 1) * 32 * 128 + tx * 8;
            const float* acp = ap + c * 32 * 128;
#pragma unroll 4
            for (int kk = 0; kk < 32; kk++) {
                float4  al = *(const float4*)(acp + kk * 128);
                float4  ah = *(const float4*)(acp + kk * 128 + 4);
                double2 bl = *(const double2*)(bp + kk * 128);
                double2 bh = *(const double2*)(bp + kk * 128 + 4);
                ull b0 = __double_as_longlong(bl.x);
                ull b1 = __double_as_longlong(bl.y);
                ull b2 = __double_as_longlong(bh.x);
                ull b3 = __double_as_longlong(bh.y);
                ull a0 = pack2(al.x, al.x), a1 = pack2(al.y, al.y);
                ull a2 = pack2(al.z, al.z), a3 = pack2(al.w, al.w);
                ull a4 = pack2(ah.x, ah.x), a5 = pack2(ah.y, ah.y);
                ull a6 = pack2(ah.z, ah.z), a7 = pack2(ah.w, ah.w);
                acc[0][0] = fma2(a0, b0, acc[0][0]); acc[0][1] = fma2(a0, b1, acc[0][1]);
                acc[0][2] = fma2(a0, b2, acc[0][2]); acc[0][3] = fma2(a0, b3, acc[0][3]);
                acc[1][0] = fma2(a1, b0, acc[1][0]); acc[1][1] = fma2(a1, b1, acc[1][1]);
                acc[1][2] = fma2(a1, b2, acc[1][2]); acc[1][3] = fma2(a1, b3, acc[1][3]);
                acc[2][0] = fma2(a2, b0, acc[2][0]); acc[2][1] = fma2(a2, b1, acc[2][1]);
                acc[2][2] = fma2(a2, b2, acc[2][2]); acc[2][3] = fma2(a2, b3, acc[2][3]);
                acc[3][0] = fma2(a3, b0, acc[3][0]); acc[3][1] = fma2(a3, b1, acc[3][1]);
                acc[3][2] = fma2(a3, b2, acc[3][2]); acc[3][3] = fma2(a3, b3, acc[3][3]);
                acc[4][0] = fma2(a4, b0, acc[4][0]); acc[4][1] = fma2(a4, b1, acc[4][1]);
                acc[4][2] = fma2(a4, b2, acc[4][2]); acc[4][3] = fma2(a4, b3, acc[4][3]);
                acc[5][0] = fma2(a5, b0, acc[5][0]); acc[5][1] = fma2(a5, b1, acc[5][1]);
                acc[5][2] = fma2(a5, b2, acc[5][2]); acc[5][3] = fma2(a5, b3, acc[5][3]);
                acc[6][0] = fma2(a6, b0, acc[6][0]); acc[6][1] = fma2(a6, b1, acc[6][1]);
                acc[6][2] = fma2(a6, b2, acc[6][2]); acc[6][3] = fma2(a6, b3, acc[6][3]);
                acc[7][0] = fma2(a7, b0, acc[7][0]); acc[7][1] = fma2(a7, b1, acc[7][1]);
                acc[7][2] = fma2(a7, b2, acc[7][2]); acc[7][3] = fma2(a7, b3, acc[7][3]);
            }
            if (c < 3) {
                // stage prefetched chunk c+1 into the other buffer
                float* d = wb + ((c + 1) & 1) * 32 * 128;
                int row = tid >> 5, cg = tid & 31;
#pragma unroll
                for (int i = 0; i < 4; i++)
                    *(float4*)(d + (i * 8 + row) * 128 + cg * 4) = wr[i];
                if (c < 2) {
#pragma unroll
                    for (int i = 0; i < 4; i++)
                        wr[i] = __ldg(w4 + (c + 2) * 1024 + i * 256 + tid);
                }
                __syncthreads();
            }
        }

        float4 bv0 = *(const float4*)(bs + tx * 8);
        float4 bv1 = *(const float4*)(bs + tx * 8 + 4);
#pragma unroll
        for (int i = 0; i < 8; i++) {
            int tr = ty * 8 + i;
            if (tr < rows) {
                float* o = g_scratch + (size_t)(rs + tr) * DD;
                float2 p0 = unpack2(acc[i][0]), p1 = unpack2(acc[i][1]);
                float2 p2 = unpack2(acc[i][2]), p3 = unpack2(acc[i][3]);
                *(float4*)(o + tx * 8)     = make_float4(p0.x + bv0.x, p0.y + bv0.y,
                                                         p1.x + bv0.z, p1.y + bv0.w);
                *(float4*)(o + tx * 8 + 4) = make_float4(p2.x + bv1.x, p2.y + bv1.y,
                                                         p3.x + bv1.z, p3.y + bv1.w);
            }
        }
        __syncthreads();   // protect smem before next tile's fills
    }
}

// ---------------- K5: weighted combine ----------------------------------------
__global__ __launch_bounds__(256) void k5_combine(float* __restrict__ out) {
    int idx = blockIdx.x * 256 + threadIdx.x;
    int b = idx >> 5;
    int c = (idx & 31) * 4;
    float4 r = make_float4(0.f, 0.f, 0.f, 0.f);
#pragma unroll
    for (int j = 0; j < 3; j++) {
        float w = g_w[b * 3 + j];
        int   p = g_pos[b * 3 + j];
        float4 sv = *(const float4*)(g_scratch + (size_t)p * DD + c);
        r.x += w * sv.x;
        r.y += w * sv.y;
        r.z += w * sv.z;
        r.w += w * sv.w;
    }
    *(float4*)(out + (size_t)b * DD + c) = r;
}

// ---------------- launch ------------------------------------------------------
extern "C" void kernel_launch(void* const* d_in, const int* in_sizes, int n_in,
                              void* d_out, int out_size) {
    const float* x    = (const float*)d_in[0];
    const float* dsc  = (const float*)d_in[1];
    const float* cent = (const float*)d_in[2];
    const float* W    = (const float*)d_in[3];
    const float* bias = (const float*)d_in[4];
    float* out = (float*)d_out;

    cudaFuncSetAttribute(k1_route, cudaFuncAttributeMaxDynamicSharedMemorySize, K1_SMEM);
    cudaFuncSetAttribute(k4_gemm,  cudaFuncAttributeMaxDynamicSharedMemorySize, K4_SMEM);

    k1_route<<<NBLK, 256, K1_SMEM>>>(x, dsc, cent);
    k2_scan<<<1, 256>>>();
    k3_scatter<<<BB / 256, 256>>>();
    k4_gemm<<<K4_GRID, 256, K4_SMEM>>>(x, W, bias);
    k5_combine<<<BB * 32 / 256, 256>>>(out);
}

// round 6
// speedup vs baseline: 1.1138x; 1.0792x over previous
#include <cuda_runtime.h>
#include <cstdint>

#define BB 16384
#define EE 64
#define DD 128
#define ES 3
#define NBLK (BB / 64)          // 256 k1 blocks

typedef unsigned long long ull;

// ---------------- device scratch (static; no allocations allowed) -------------
__device__ int    g_offsets[EE + 1];
__device__ int    g_ntiles;
__device__ int    g_picked[BB * ES];
__device__ int    g_loc[BB * ES];
__device__ float  g_w[BB * ES];
__device__ int    g_entry_token[BB * ES];
__device__ int    g_pos[BB * ES];
__device__ int2   g_tiles[1024];
__device__ int    g_blockhist[NBLK * EE];
__device__ int    g_blockbase[NBLK * EE];
__device__ float  g_wt[(size_t)EE * DD * DD];        // tf32-rounded W^T [e][o][k]
__device__ float  g_scratch[(size_t)BB * ES * DD];   // 25 MB

// ---------------- packed f32x2 helpers (k1 only) ------------------------------
__device__ __forceinline__ ull pack2(float lo, float hi) {
    ull r;
    asm("mov.b64 %0, {%1, %2};" : "=l"(r) : "f"(lo), "f"(hi));
    return r;
}
__device__ __forceinline__ float2 unpack2(ull v) {
    float2 f;
    asm("mov.b64 {%0, %1}, %2;" : "=f"(f.x), "=f"(f.y) : "l"(v));
    return f;
}
__device__ __forceinline__ ull fma2(ull a, ull b, ull c) {
    ull d;
    asm("fma.rn.f32x2 %0, %1, %2, %3;" : "=l"(d) : "l"(a), "l"(b), "l"(c));
    return d;
}
__device__ __forceinline__ ull add2(ull a, ull b) {
    ull d;
    asm("add.rn.f32x2 %0, %1, %2;" : "=l"(d) : "l"(a), "l"(b));
    return d;
}
__device__ __forceinline__ float to_tf32(float x) {
    float r;
    asm("cvt.rna.tf32.f32 %0, %1;" : "=f"(r) : "f"(x));
    return r;
}

// m16n8k8 row.col tf32 MMA, D += A*B (C==D accumulate in place)
__device__ __forceinline__ void mma_tf32(float* c, const uint32_t* a,
                                         const uint32_t* b) {
    asm volatile(
        "mma.sync.aligned.m16n8k8.row.col.f32.tf32.tf32.f32 "
        "{%0,%1,%2,%3}, {%4,%5,%6,%7}, {%8,%9}, {%0,%1,%2,%3};"
        : "+f"(c[0]), "+f"(c[1]), "+f"(c[2]), "+f"(c[3])
        : "r"(a[0]), "r"(a[1]), "r"(a[2]), "r"(a[3]), "r"(b[0]), "r"(b[1]));
}

// ---------------- K1: accurate routing (unchanged, passing) --------------------
#define K1_XP 68
#define K1_CP 36
#define K1_TP 36
#define K1_SMEM ((128 * K1_XP + 128 * K1_CP + 64 * K1_TP + 64 + 64) * 4)

__global__ __launch_bounds__(256) void k1_route(const float* __restrict__ x,
                                                const float* __restrict__ dscale,
                                                const float* __restrict__ cent) {
    extern __shared__ float sm[];
    float*  xs   = sm;
    float*  cs   = xs + 128 * K1_XP;
    float*  ts   = cs + 128 * K1_CP;
    double* nc2s = (double*)(ts + 64 * K1_TP);
    int*    hist = (int*)(nc2s + 32);

    int tid = threadIdx.x;
    if (tid < 64) hist[tid] = 0;
    int t0 = blockIdx.x * 64;

    const float4* x4 = (const float4*)x;
#pragma unroll
    for (int i = 0; i < 8; i++) {
        int f = i * 256 + tid;
        int tr = f & 63, kc = f >> 6;
        float4 v = __ldg(x4 + (size_t)(t0 + tr) * 32 + kc);
        xs[(kc * 4 + 0) * K1_XP + tr] = v.x;
        xs[(kc * 4 + 1) * K1_XP + tr] = v.y;
        xs[(kc * 4 + 2) * K1_XP + tr] = v.z;
        xs[(kc * 4 + 3) * K1_XP + tr] = v.w;
    }
    const float4* c4 = (const float4*)cent;
#pragma unroll
    for (int i = 0; i < 4; i++) {
        int f = i * 256 + tid;
        int er = f & 31, kc = f >> 5;
        float4 v = __ldg(c4 + (size_t)er * 32 + kc);
        cs[(kc * 4 + 0) * K1_CP + er] = v.x;
        cs[(kc * 4 + 1) * K1_CP + er] = v.y;
        cs[(kc * 4 + 2) * K1_CP + er] = v.z;
        cs[(kc * 4 + 3) * K1_CP + er] = v.w;
    }
    __syncthreads();

    if (tid < 32) {
        double a0 = 0.0, a1 = 0.0;
#pragma unroll 8
        for (int k = 0; k < 128; k += 2) {
            double u0 = (double)cs[(k + 0) * K1_CP + tid]; a0 = fma(u0, u0, a0);
            double u1 = (double)cs[(k + 1) * K1_CP + tid]; a1 = fma(u1, u1, a1);
        }
        nc2s[tid] = a0 + a1;
    }

    {
        int tx = tid & 7, ty = tid >> 3;
        ull acc[2][2][4];
#pragma unroll
        for (int i = 0; i < 2; i++)
#pragma unroll
            for (int j = 0; j < 2; j++)
#pragma unroll
                for (int s = 0; s < 4; s++) acc[i][j][s] = 0ULL;

        const float* ap = xs + ty * 2;
        const float* bp = cs + tx * 4;
#pragma unroll 4
        for (int k = 0; k < 128; k += 4) {
#pragma unroll
            for (int s = 0; s < 4; s++) {
                float2  a  = *(const float2*)(ap + (k + s) * K1_XP);
                double2 nb = *(const double2*)(bp + (k + s) * K1_CP);
                ull b01 = __double_as_longlong(nb.x);
                ull b23 = __double_as_longlong(nb.y);
                ull a0 = pack2(a.x, a.x), a1 = pack2(a.y, a.y);
                acc[0][0][s] = fma2(a0, b01, acc[0][0][s]);
                acc[0][1][s] = fma2(a0, b23, acc[0][1][s]);
                acc[1][0][s] = fma2(a1, b01, acc[1][0][s]);
                acc[1][1][s] = fma2(a1, b23, acc[1][1][s]);
            }
        }
#pragma unroll
        for (int i = 0; i < 2; i++) {
            ull s01 = add2(add2(acc[i][0][0], acc[i][0][1]),
                           add2(acc[i][0][2], acc[i][0][3]));
            ull s23 = add2(add2(acc[i][1][0], acc[i][1][1]),
                           add2(acc[i][1][2], acc[i][1][3]));
            float2 v01 = unpack2(s01), v23 = unpack2(s23);
            int tok = ty * 2 + i;
            *(float4*)(ts + tok * K1_TP + tx * 4) =
                make_float4(v01.x, v01.y, v23.x, v23.y);
        }
    }
    __syncthreads();

    if (tid < 64) {
        int tok = tid;
        double a0 = 0.0, a1 = 0.0, a2 = 0.0, a3 = 0.0;
#pragma unroll 8
        for (int k = 0; k < 128; k += 4) {
            double u0 = (double)xs[(k + 0) * K1_XP + tok]; a0 = fma(u0, u0, a0);
            double u1 = (double)xs[(k + 1) * K1_XP + tok]; a1 = fma(u1, u1, a1);
            double u2 = (double)xs[(k + 2) * K1_XP + tok]; a2 = fma(u2, u2, a2);
            double u3 = (double)xs[(k + 3) * K1_XP + tok]; a3 = fma(u3, u3, a3);
        }
        double nx2 = (a0 + a1) + (a2 + a3);

        float  s  = __ldg(dscale);
        double Kd = ((double)s * (double)s) * (1.0 / 128.0);

        double v0 = 1e300, v1 = 1e300, v2 = 1e300;
        int    i0 = 0, i1 = 0, i2 = 0;
        for (int e = 0; e < 64; e++) {
            int    ei = e & 31;
            double t  = (double)ts[tok * K1_TP + ei];
            double br = nx2 + nc2s[ei];
            double dd = Kd * (e < 32 ? fma(-2.0, t, br) : fma(2.0, t, br));
            if (dd < v0)      { v2 = v1; i2 = i1; v1 = v0; i1 = i0; v0 = dd; i0 = e; }
            else if (dd < v1) { v2 = v1; i2 = i1; v1 = dd; i1 = e; }
            else if (dd < v2) { v2 = dd; i2 = e; }
        }
        float d0 = (float)(Kd * fma(-2.0, (double)ts[tok * K1_TP + 0], nx2 + nc2s[0]));
        float d1 = (float)(Kd * fma(-2.0, (double)ts[tok * K1_TP + 1], nx2 + nc2s[1]));
        float d2 = (float)(Kd * fma(-2.0, (double)ts[tok * K1_TP + 2], nx2 + nc2s[2]));
        float w0 = 1.0f / (1.0f + d0);
        float w1 = 1.0f / (1.0f + d1);
        float w2 = 1.0f / (1.0f + d2);
        float z  = w0 + w1 + w2;
        int b = t0 + tok;
        g_picked[b * 3 + 0] = i0; g_picked[b * 3 + 1] = i1; g_picked[b * 3 + 2] = i2;
        g_w[b * 3 + 0] = w0 / z; g_w[b * 3 + 1] = w1 / z; g_w[b * 3 + 2] = w2 / z;
        g_loc[b * 3 + 0] = atomicAdd(&hist[i0], 1);
        g_loc[b * 3 + 1] = atomicAdd(&hist[i1], 1);
        g_loc[b * 3 + 2] = atomicAdd(&hist[i2], 1);
    }
    __syncthreads();
    if (tid < 64) g_blockhist[blockIdx.x * 64 + tid] = hist[tid];
}

// ---------------- k_wt: tf32-rounded W^T [e][o][k], plain layout ----------------
#define KWT_SMEM (128 * 132 * 4)
__global__ __launch_bounds__(256) void k_wt(const float* __restrict__ W) {
    extern __shared__ float wsm[];   // [128][132]  wsm[k][o]
    int e = blockIdx.x, tid = threadIdx.x;
    const float4* w4 = (const float4*)(W + (size_t)e * DD * DD);
#pragma unroll
    for (int i = 0; i < 16; i++) {
        int idx = i * 256 + tid;                 // k = idx>>5, o4 = idx&31
        float4 v = __ldg(w4 + idx);
        *(float4*)(wsm + (idx >> 5) * 132 + (idx & 31) * 4) = v;
    }
    __syncthreads();
    float4* dst = (float4*)(g_wt + (size_t)e * DD * DD);
#pragma unroll
    for (int i = 0; i < 16; i++) {
        int idx = i * 256 + tid;                 // o = idx>>5, kq = idx&31
        int o = idx >> 5, kq = idx & 31;
        float4 v;
        v.x = to_tf32(wsm[(kq * 4 + 0) * 132 + o]);
        v.y = to_tf32(wsm[(kq * 4 + 1) * 132 + o]);
        v.z = to_tf32(wsm[(kq * 4 + 2) * 132 + o]);
        v.w = to_tf32(wsm[(kq * 4 + 3) * 132 + o]);
        dst[o * 32 + kq] = v;
    }
}

// ---------------- K2: scan over (block, expert) histograms ---------------------
__global__ __launch_bounds__(256) void k2_scan() {
    __shared__ int csum[4 * 64];
    __shared__ int cnts[64];
    __shared__ int off[65];
    __shared__ int toff[64];
    int tid = threadIdx.x;
    int e = tid & 63, c = tid >> 6;

    int s = 0;
#pragma unroll 8
    for (int i = 0; i < 64; i++) s += g_blockhist[((c << 6) + i) * 64 + e];
    csum[c * 64 + e] = s;
    __syncthreads();

    if (tid < 64) {
        int t0 = csum[0 * 64 + tid], t1 = csum[1 * 64 + tid];
        int t2 = csum[2 * 64 + tid], t3 = csum[3 * 64 + tid];
        cnts[tid] = t0 + t1 + t2 + t3;
        csum[0 * 64 + tid] = 0;
        csum[1 * 64 + tid] = t0;
        csum[2 * 64 + tid] = t0 + t1;
        csum[3 * 64 + tid] = t0 + t1 + t2;
    }
    __syncthreads();

    if (tid == 0) {
        int o = 0, to = 0;
        for (int i = 0; i < 64; i++) {
            off[i] = o; toff[i] = to;
            o += cnts[i]; to += (cnts[i] + 127) >> 7;
        }
        off[64] = o; g_ntiles = to;
    }
    __syncthreads();

    if (tid < 64) {
        g_offsets[tid] = off[tid];
        int nt = (cnts[tid] + 127) >> 7;
        for (int i = 0; i < nt; i++)
            g_tiles[toff[tid] + i] = make_int2(tid, off[tid] + (i << 7));
    }
    if (tid == 0) g_offsets[64] = off[64];
    __syncthreads();

    int run = off[e] + csum[c * 64 + e];
    for (int i = 0; i < 64; i++) {
        int idx = ((c << 6) + i) * 64 + e;
        int v = g_blockhist[idx];
        g_blockbase[idx] = run;
        run += v;
    }
}

// ---------------- K3: scatter --------------------------------------------------
__global__ __launch_bounds__(256) void k3_scatter() {
    int b = blockIdx.x * 256 + threadIdx.x;
    int blk = b >> 6;
#pragma unroll
    for (int j = 0; j < 3; j++) {
        int e = g_picked[b * 3 + j];
        int p = g_blockbase[blk * 64 + e] + g_loc[b * 3 + j];
        g_entry_token[p] = b;
        g_pos[b * 3 + j] = p;
    }
}

// ---------------- K4: TF32 mma.sync grouped GEMM, 128x128 tile -----------------
// smem: As[128][132] + Bs[128][132] = 132KB, 1 CTA/SM.
// 8 warps: warp w -> rows (w&3)*32..+32, cols (w>>2)*64..+64.
#define K4_LD 132
#define K4_SMEM (2 * 128 * K4_LD * 4)
#define K4_GRID 448

__global__ __launch_bounds__(256) void k4_gemm(const float* __restrict__ x,
                                               const float* __restrict__ bias) {
    int t = blockIdx.x;
    if (t >= g_ntiles) return;
    int2 tl = g_tiles[t];
    int e = tl.x, rs = tl.y;
    int rows = g_offsets[e + 1] - rs;
    if (rows > 128) rows = 128;

    extern __shared__ float sm[];
    float* As = sm;                  // [128][K4_LD]  token rows (tf32)
    float* Bs = sm + 128 * K4_LD;    // [128][K4_LD]  W^T rows (tf32)

    int tid = threadIdx.x;

    // B: copy pre-rounded W^T
    const float4* wt4 = (const float4*)(g_wt + (size_t)e * DD * DD);
#pragma unroll
    for (int i = 0; i < 16; i++) {
        int idx = i * 256 + tid;
        int o = idx >> 5, kq = idx & 31;
        *(float4*)(Bs + o * K4_LD + kq * 4) = __ldg(wt4 + idx);
    }

    // A: gather token rows, tf32-round
    {
        int tr = tid & 127, h = tid >> 7;      // 2 threads per row
        bool valid = tr < rows;
        int tok = valid ? g_entry_token[rs + tr] : 0;
        const float4* xr = (const float4*)x + (size_t)tok * 32;
#pragma unroll
        for (int i = 0; i < 16; i++) {
            int kc = i * 2 + h;                 // float4 index 0..31
            float4 v = make_float4(0.f, 0.f, 0.f, 0.f);
            if (valid) v = __ldg(xr + kc);
            v.x = to_tf32(v.x); v.y = to_tf32(v.y);
            v.z = to_tf32(v.z); v.w = to_tf32(v.w);
            *(float4*)(As + tr * K4_LD + kc * 4) = v;
        }
    }
    __syncthreads();

    int wid = tid >> 5, lane = tid & 31;
    int gid = lane >> 2, tig = lane & 3;
    int m0 = (wid & 3) * 32, n0 = (wid >> 2) * 64;

    float acc[2][8][4];
#pragma unroll
    for (int i = 0; i < 2; i++)
#pragma unroll
        for (int j = 0; j < 8; j++)
#pragma unroll
            for (int r = 0; r < 4; r++) acc[i][j][r] = 0.f;

    const float* arow = As + (m0 + gid) * K4_LD + tig;
    const float* brow = Bs + (n0 + gid) * K4_LD + tig;

#pragma unroll 4
    for (int kb = 0; kb < 128; kb += 8) {
        uint32_t a[2][4];
#pragma unroll
        for (int i = 0; i < 2; i++) {
            const float* p = arow + i * 16 * K4_LD + kb;
            a[i][0] = __float_as_uint(p[0]);
            a[i][1] = __float_as_uint(p[8 * K4_LD]);
            a[i][2] = __float_as_uint(p[4]);
            a[i][3] = __float_as_uint(p[8 * K4_LD + 4]);
        }
        uint32_t b[8][2];
#pragma unroll
        for (int j = 0; j < 8; j++) {
            const float* p = brow + j * 8 * K4_LD + kb;
            b[j][0] = __float_as_uint(p[0]);
            b[j][1] = __float_as_uint(p[4]);
        }
#pragma unroll
        for (int i = 0; i < 2; i++)
#pragma unroll
            for (int j = 0; j < 8; j++)
                mma_tf32(acc[i][j], a[i], b[j]);
    }

    // epilogue: D rows m0+i*16+gid(+8), cols n0+j*8+tig*2(+1); add bias
    const float* be = bias + (size_t)e * DD;
#pragma unroll
    for (int i = 0; i < 2; i++) {
        int r0 = m0 + i * 16 + gid;
        int r1 = r0 + 8;
        bool v0 = r0 < rows, v1 = r1 < rows;
        float* o0 = g_scratch + (size_t)(rs + r0) * DD;
        float* o1 = g_scratch + (size_t)(rs + r1) * DD;
#pragma unroll
        for (int j = 0; j < 8; j++) {
            int col = n0 + j * 8 + tig * 2;
            float2 bv = *(const float2*)(be + col);
            if (v0) *(float2*)(o0 + col) =
                make_float2(acc[i][j][0] + bv.x, acc[i][j][1] + bv.y);
            if (v1) *(float2*)(o1 + col) =
                make_float2(acc[i][j][2] + bv.x, acc[i][j][3] + bv.y);
        }
    }
}

// ---------------- K5: weighted combine ----------------------------------------
__global__ __launch_bounds__(256) void k5_combine(float* __restrict__ out) {
    int idx = blockIdx.x * 256 + threadIdx.x;
    int b = idx >> 5;
    int c = (idx & 31) * 4;
    float4 r = make_float4(0.f, 0.f, 0.f, 0.f);
#pragma unroll
    for (int j = 0; j < 3; j++) {
        float w = g_w[b * 3 + j];
        int   p = g_pos[b * 3 + j];
        float4 sv = *(const float4*)(g_scratch + (size_t)p * DD + c);
        r.x += w * sv.x;
        r.y += w * sv.y;
        r.z += w * sv.z;
        r.w += w * sv.w;
    }
    *(float4*)(out + (size_t)b * DD + c) = r;
}

// ---------------- launch ------------------------------------------------------
extern "C" void kernel_launch(void* const* d_in, const int* in_sizes, int n_in,
                              void* d_out, int out_size) {
    const float* x    = (const float*)d_in[0];
    const float* dsc  = (const float*)d_in[1];
    const float* cent = (const float*)d_in[2];
    const float* W    = (const float*)d_in[3];
    const float* bias = (const float*)d_in[4];
    float* out = (float*)d_out;

    cudaFuncSetAttribute(k1_route, cudaFuncAttributeMaxDynamicSharedMemorySize, K1_SMEM);
    cudaFuncSetAttribute(k_wt,     cudaFuncAttributeMaxDynamicSharedMemorySize, KWT_SMEM);
    cudaFuncSetAttribute(k4_gemm,  cudaFuncAttributeMaxDynamicSharedMemorySize, K4_SMEM);

    k_wt<<<EE, 256, KWT_SMEM>>>(W);
    k1_route<<<NBLK, 256, K1_SMEM>>>(x, dsc, cent);
    k2_scan<<<1, 256>>>();
    k3_scatter<<<BB / 256, 256>>>();
    k4_gemm<<<K4_GRID, 256, K4_SMEM>>>(x, bias);
    k5_combine<<<BB * 32 / 256, 256>>>(out);
}

// round 7
// speedup vs baseline: 1.1164x; 1.0023x over previous
#include <cuda_runtime.h>
#include <cstdint>

#define BB 16384
#define EE 64
#define DD 128
#define ES 3
#define NBLK (BB / 64)          // 256 route blocks
#define GRID 148

typedef unsigned long long ull;

// ---------------- device scratch (static; no allocations allowed) -------------
__device__ int    g_offsets[EE + 1];
__device__ int    g_ntiles;
__device__ int    g_picked[BB * ES];
__device__ int    g_loc[BB * ES];
__device__ float  g_w[BB * ES];
__device__ int    g_entry_token[BB * ES];
__device__ int    g_pos[BB * ES];
__device__ int2   g_tiles[1024];
__device__ int    g_blockhist[NBLK * EE];
__device__ int    g_blockbase[NBLK * EE];
__device__ float  g_wt[(size_t)EE * DD * DD];        // tf32-rounded W^T [e][o][k]
__device__ float  g_scratch[(size_t)BB * ES * DD];   // 25 MB

// ---------------- grid barrier (sense-reversing, replay-safe) ------------------
__device__ int          g_bar_count = 0;
__device__ volatile int g_bar_gen   = 0;

__device__ __forceinline__ void grid_sync() {
    __syncthreads();
    if (threadIdx.x == 0) {
        __threadfence();
        int gen = g_bar_gen;
        if (atomicAdd(&g_bar_count, 1) == GRID - 1) {
            g_bar_count = 0;
            __threadfence();
            g_bar_gen = gen + 1;
        } else {
            while (g_bar_gen == gen) __nanosleep(64);
        }
        __threadfence();
    }
    __syncthreads();
}

// ---------------- helpers ------------------------------------------------------
__device__ __forceinline__ ull pack2(float lo, float hi) {
    ull r;
    asm("mov.b64 %0, {%1, %2};" : "=l"(r) : "f"(lo), "f"(hi));
    return r;
}
__device__ __forceinline__ float2 unpack2(ull v) {
    float2 f;
    asm("mov.b64 {%0, %1}, %2;" : "=f"(f.x), "=f"(f.y) : "l"(v));
    return f;
}
__device__ __forceinline__ ull fma2(ull a, ull b, ull c) {
    ull d;
    asm("fma.rn.f32x2 %0, %1, %2, %3;" : "=l"(d) : "l"(a), "l"(b), "l"(c));
    return d;
}
__device__ __forceinline__ ull add2(ull a, ull b) {
    ull d;
    asm("add.rn.f32x2 %0, %1, %2;" : "=l"(d) : "l"(a), "l"(b));
    return d;
}
__device__ __forceinline__ float to_tf32(float x) {
    float r;
    asm("cvt.rna.tf32.f32 %0, %1;" : "=f"(r) : "f"(x));
    return r;
}
__device__ __forceinline__ void mma_tf32(float* c, const uint32_t* a,
                                         const uint32_t* b) {
    asm volatile(
        "mma.sync.aligned.m16n8k8.row.col.f32.tf32.tf32.f32 "
        "{%0,%1,%2,%3}, {%4,%5,%6,%7}, {%8,%9}, {%0,%1,%2,%3};"
        : "+f"(c[0]), "+f"(c[1]), "+f"(c[2]), "+f"(c[3])
        : "r"(a[0]), "r"(a[1]), "r"(a[2]), "r"(a[3]), "r"(b[0]), "r"(b[1]));
}

// smem layout sizes
#define K1_XP 68
#define K1_CP 36
#define K1_TP 36
#define K4_LD 132
#define FUSED_SMEM (2 * 128 * K4_LD * 4)    // 132KB, max of all phases

// ---------------- fused persistent kernel --------------------------------------
__global__ __launch_bounds__(256) void fused(const float* __restrict__ x,
                                             const float* __restrict__ dscale,
                                             const float* __restrict__ cent,
                                             const float* __restrict__ W,
                                             const float* __restrict__ bias,
                                             float* __restrict__ out) {
    extern __shared__ float sm[];
    int tid = threadIdx.x;
    int cta = blockIdx.x;

    // ================= Phase A1: CTAs 0..63 build tf32 W^T ====================
    if (cta < EE) {
        float* wsm = sm;                         // [128][132] W_e natural wsm[k][o]
        const float4* w4 = (const float4*)(W + (size_t)cta * DD * DD);
#pragma unroll
        for (int i = 0; i < 16; i++) {
            int idx = i * 256 + tid;
            float4 v = __ldg(w4 + idx);
            *(float4*)(wsm + (idx >> 5) * 132 + (idx & 31) * 4) = v;
        }
        __syncthreads();
        float4* dst = (float4*)(g_wt + (size_t)cta * DD * DD);
#pragma unroll
        for (int i = 0; i < 16; i++) {
            int idx = i * 256 + tid;
            int o = idx >> 5, kq = idx & 31;
            float4 v;
            v.x = to_tf32(wsm[(kq * 4 + 0) * 132 + o]);
            v.y = to_tf32(wsm[(kq * 4 + 1) * 132 + o]);
            v.z = to_tf32(wsm[(kq * 4 + 2) * 132 + o]);
            v.w = to_tf32(wsm[(kq * 4 + 3) * 132 + o]);
            dst[o * 32 + kq] = v;
        }
        __syncthreads();
    }

    // ================= Phase A2: routing (stride over 256 blocks) ==============
    {
        float*  xs   = sm;                          // [128][K1_XP]
        float*  cs   = xs + 128 * K1_XP;            // [128][K1_CP]
        float*  ts   = cs + 128 * K1_CP;            // [64][K1_TP]
        double* nc2s = (double*)(ts + 64 * K1_TP);  // [32]
        int*    hist = (int*)(nc2s + 32);           // [64]
        const float4* x4 = (const float4*)x;
        const float4* c4 = (const float4*)cent;

        for (int blk = cta; blk < NBLK; blk += GRID) {
            if (tid < 64) hist[tid] = 0;
            int t0 = blk * 64;

#pragma unroll
            for (int i = 0; i < 8; i++) {
                int f = i * 256 + tid;
                int tr = f & 63, kc = f >> 6;
                float4 v = __ldg(x4 + (size_t)(t0 + tr) * 32 + kc);
                xs[(kc * 4 + 0) * K1_XP + tr] = v.x;
                xs[(kc * 4 + 1) * K1_XP + tr] = v.y;
                xs[(kc * 4 + 2) * K1_XP + tr] = v.z;
                xs[(kc * 4 + 3) * K1_XP + tr] = v.w;
            }
#pragma unroll
            for (int i = 0; i < 4; i++) {
                int f = i * 256 + tid;
                int er = f & 31, kc = f >> 5;
                float4 v = __ldg(c4 + (size_t)er * 32 + kc);
                cs[(kc * 4 + 0) * K1_CP + er] = v.x;
                cs[(kc * 4 + 1) * K1_CP + er] = v.y;
                cs[(kc * 4 + 2) * K1_CP + er] = v.z;
                cs[(kc * 4 + 3) * K1_CP + er] = v.w;
            }
            __syncthreads();

            if (tid < 32) {
                double a0 = 0.0, a1 = 0.0;
#pragma unroll 8
                for (int k = 0; k < 128; k += 2) {
                    double u0 = (double)cs[(k + 0) * K1_CP + tid]; a0 = fma(u0, u0, a0);
                    double u1 = (double)cs[(k + 1) * K1_CP + tid]; a1 = fma(u1, u1, a1);
                }
                nc2s[tid] = a0 + a1;
            }

            {
                int tx = tid & 7, ty = tid >> 3;
                ull acc[2][2][4];
#pragma unroll
                for (int i = 0; i < 2; i++)
#pragma unroll
                    for (int j = 0; j < 2; j++)
#pragma unroll
                        for (int s = 0; s < 4; s++) acc[i][j][s] = 0ULL;

                const float* ap = xs + ty * 2;
                const float* bp = cs + tx * 4;
#pragma unroll 4
                for (int k = 0; k < 128; k += 4) {
#pragma unroll
                    for (int s = 0; s < 4; s++) {
                        float2  a  = *(const float2*)(ap + (k + s) * K1_XP);
                        double2 nb = *(const double2*)(bp + (k + s) * K1_CP);
                        ull b01 = __double_as_longlong(nb.x);
                        ull b23 = __double_as_longlong(nb.y);
                        ull a0 = pack2(a.x, a.x), a1 = pack2(a.y, a.y);
                        acc[0][0][s] = fma2(a0, b01, acc[0][0][s]);
                        acc[0][1][s] = fma2(a0, b23, acc[0][1][s]);
                        acc[1][0][s] = fma2(a1, b01, acc[1][0][s]);
                        acc[1][1][s] = fma2(a1, b23, acc[1][1][s]);
                    }
                }
#pragma unroll
                for (int i = 0; i < 2; i++) {
                    ull s01 = add2(add2(acc[i][0][0], acc[i][0][1]),
                                   add2(acc[i][0][2], acc[i][0][3]));
                    ull s23 = add2(add2(acc[i][1][0], acc[i][1][1]),
                                   add2(acc[i][1][2], acc[i][1][3]));
                    float2 v01 = unpack2(s01), v23 = unpack2(s23);
                    int tok = ty * 2 + i;
                    *(float4*)(ts + tok * K1_TP + tx * 4) =
                        make_float4(v01.x, v01.y, v23.x, v23.y);
                }
            }
            __syncthreads();

            if (tid < 64) {
                int tok = tid;
                double a0 = 0.0, a1 = 0.0, a2 = 0.0, a3 = 0.0;
#pragma unroll 8
                for (int k = 0; k < 128; k += 4) {
                    double u0 = (double)xs[(k + 0) * K1_XP + tok]; a0 = fma(u0, u0, a0);
                    double u1 = (double)xs[(k + 1) * K1_XP + tok]; a1 = fma(u1, u1, a1);
                    double u2 = (double)xs[(k + 2) * K1_XP + tok]; a2 = fma(u2, u2, a2);
                    double u3 = (double)xs[(k + 3) * K1_XP + tok]; a3 = fma(u3, u3, a3);
                }
                double nx2 = (a0 + a1) + (a2 + a3);

                float  s  = __ldg(dscale);
                double Kd = ((double)s * (double)s) * (1.0 / 128.0);

                double v0 = 1e300, v1 = 1e300, v2 = 1e300;
                int    i0 = 0, i1 = 0, i2 = 0;
                for (int e = 0; e < 64; e++) {
                    int    ei = e & 31;
                    double t  = (double)ts[tok * K1_TP + ei];
                    double br = nx2 + nc2s[ei];
                    double dd = Kd * (e < 32 ? fma(-2.0, t, br) : fma(2.0, t, br));
                    if (dd < v0)      { v2 = v1; i2 = i1; v1 = v0; i1 = i0; v0 = dd; i0 = e; }
                    else if (dd < v1) { v2 = v1; i2 = i1; v1 = dd; i1 = e; }
                    else if (dd < v2) { v2 = dd; i2 = e; }
                }
                float d0 = (float)(Kd * fma(-2.0, (double)ts[tok * K1_TP + 0], nx2 + nc2s[0]));
                float d1 = (float)(Kd * fma(-2.0, (double)ts[tok * K1_TP + 1], nx2 + nc2s[1]));
                float d2 = (float)(Kd * fma(-2.0, (double)ts[tok * K1_TP + 2], nx2 + nc2s[2]));
                float w0 = 1.0f / (1.0f + d0);
                float w1 = 1.0f / (1.0f + d1);
                float w2 = 1.0f / (1.0f + d2);
                float z  = w0 + w1 + w2;
                int b = t0 + tok;
                g_picked[b * 3 + 0] = i0; g_picked[b * 3 + 1] = i1; g_picked[b * 3 + 2] = i2;
                g_w[b * 3 + 0] = w0 / z; g_w[b * 3 + 1] = w1 / z; g_w[b * 3 + 2] = w2 / z;
                g_loc[b * 3 + 0] = atomicAdd(&hist[i0], 1);
                g_loc[b * 3 + 1] = atomicAdd(&hist[i1], 1);
                g_loc[b * 3 + 2] = atomicAdd(&hist[i2], 1);
            }
            __syncthreads();
            if (tid < 64) g_blockhist[blk * 64 + tid] = hist[tid];
            __syncthreads();   // protect smem before next block iteration
        }
    }

    grid_sync();

    // ================= Phase B: scan (CTA 0 only) ==============================
    if (cta == 0) {
        int* csum = (int*)sm;        // [256]
        int* cnts = csum + 256;      // [64]
        int* off  = cnts + 64;       // [65]
        int* toff = off + 65;        // [64]
        int e = tid & 63, c = tid >> 6;

        int s = 0;
#pragma unroll 8
        for (int i = 0; i < 64; i++) s += g_blockhist[((c << 6) + i) * 64 + e];
        csum[c * 64 + e] = s;
        __syncthreads();

        if (tid < 64) {
            int t0 = csum[0 * 64 + tid], t1 = csum[1 * 64 + tid];
            int t2 = csum[2 * 64 + tid], t3 = csum[3 * 64 + tid];
            cnts[tid] = t0 + t1 + t2 + t3;
            csum[0 * 64 + tid] = 0;
            csum[1 * 64 + tid] = t0;
            csum[2 * 64 + tid] = t0 + t1;
            csum[3 * 64 + tid] = t0 + t1 + t2;
        }
        __syncthreads();

        if (tid == 0) {
            int o = 0, to = 0;
            for (int i = 0; i < 64; i++) {
                off[i] = o; toff[i] = to;
                o += cnts[i]; to += (cnts[i] + 127) >> 7;
            }
            off[64] = o; g_ntiles = to;
        }
        __syncthreads();

        if (tid < 64) {
            g_offsets[tid] = off[tid];
            int nt = (cnts[tid] + 127) >> 7;
            for (int i = 0; i < nt; i++)
                g_tiles[toff[tid] + i] = make_int2(tid, off[tid] + (i << 7));
        }
        if (tid == 0) g_offsets[64] = off[64];
        __syncthreads();

        int run = off[e] + csum[c * 64 + e];
        for (int i = 0; i < 64; i++) {
            int idx = ((c << 6) + i) * 64 + e;
            int v = g_blockhist[idx];
            g_blockbase[idx] = run;
            run += v;
        }
    }

    grid_sync();

    // ================= Phase C: scatter ========================================
    {
        int t = cta * 256 + tid;
        if (t < BB) {
            int blk = t >> 6;
#pragma unroll
            for (int j = 0; j < 3; j++) {
                int e = g_picked[t * 3 + j];
                int p = g_blockbase[blk * 64 + e] + g_loc[t * 3 + j];
                g_entry_token[p] = t;
                g_pos[t * 3 + j] = p;
            }
        }
    }

    grid_sync();

    // ================= Phase D: TF32 grouped GEMM ==============================
    {
        float* As = sm;                  // [128][K4_LD]
        float* Bs = sm + 128 * K4_LD;    // [128][K4_LD]
        int ntiles = g_ntiles;
        const float4* x4 = (const float4*)x;

        for (int t = cta; t < ntiles; t += GRID) {
            int2 tl = g_tiles[t];
            int e = tl.x, rs = tl.y;
            int rows = g_offsets[e + 1] - rs;
            if (rows > 128) rows = 128;

            __syncthreads();   // smem reuse across tiles / after phase A

            const float4* wt4 = (const float4*)(g_wt + (size_t)e * DD * DD);
#pragma unroll
            for (int i = 0; i < 16; i++) {
                int idx = i * 256 + tid;
                int o = idx >> 5, kq = idx & 31;
                *(float4*)(Bs + o * K4_LD + kq * 4) = __ldg(wt4 + idx);
            }

            {
                int tr = tid & 127, h = tid >> 7;
                bool valid = tr < rows;
                int tok = valid ? g_entry_token[rs + tr] : 0;
                const float4* xr = x4 + (size_t)tok * 32;
#pragma unroll
                for (int i = 0; i < 16; i++) {
                    int kc = i * 2 + h;
                    float4 v = make_float4(0.f, 0.f, 0.f, 0.f);
                    if (valid) v = __ldg(xr + kc);
                    v.x = to_tf32(v.x); v.y = to_tf32(v.y);
                    v.z = to_tf32(v.z); v.w = to_tf32(v.w);
                    *(float4*)(As + tr * K4_LD + kc * 4) = v;
                }
            }
            __syncthreads();

            int wid = tid >> 5, lane = tid & 31;
            int gid = lane >> 2, tig = lane & 3;
            int m0 = (wid & 3) * 32, n0 = (wid >> 2) * 64;

            float acc[2][8][4];
#pragma unroll
            for (int i = 0; i < 2; i++)
#pragma unroll
                for (int j = 0; j < 8; j++)
#pragma unroll
                    for (int r = 0; r < 4; r++) acc[i][j][r] = 0.f;

            const float* arow = As + (m0 + gid) * K4_LD + tig;
            const float* brow = Bs + (n0 + gid) * K4_LD + tig;

#pragma unroll 4
            for (int kb = 0; kb < 128; kb += 8) {
                uint32_t a[2][4];
#pragma unroll
                for (int i = 0; i < 2; i++) {
                    const float* p = arow + i * 16 * K4_LD + kb;
                    a[i][0] = __float_as_uint(p[0]);
                    a[i][1] = __float_as_uint(p[8 * K4_LD]);
                    a[i][2] = __float_as_uint(p[4]);
                    a[i][3] = __float_as_uint(p[8 * K4_LD + 4]);
                }
                uint32_t b[8][2];
#pragma unroll
                for (int j = 0; j < 8; j++) {
                    const float* p = brow + j * 8 * K4_LD + kb;
                    b[j][0] = __float_as_uint(p[0]);
                    b[j][1] = __float_as_uint(p[4]);
                }
#pragma unroll
                for (int i = 0; i < 2; i++)
#pragma unroll
                    for (int j = 0; j < 8; j++)
                        mma_tf32(acc[i][j], a[i], b[j]);
            }

            const float* be = bias + (size_t)e * DD;
#pragma unroll
            for (int i = 0; i < 2; i++) {
                int r0 = m0 + i * 16 + gid;
                int r1 = r0 + 8;
                bool v0 = r0 < rows, v1 = r1 < rows;
                float* o0 = g_scratch + (size_t)(rs + r0) * DD;
                float* o1 = g_scratch + (size_t)(rs + r1) * DD;
#pragma unroll
                for (int j = 0; j < 8; j++) {
                    int col = n0 + j * 8 + tig * 2;
                    float2 bv = *(const float2*)(be + col);
                    if (v0) *(float2*)(o0 + col) =
                        make_float2(acc[i][j][0] + bv.x, acc[i][j][1] + bv.y);
                    if (v1) *(float2*)(o1 + col) =
                        make_float2(acc[i][j][2] + bv.x, acc[i][j][3] + bv.y);
                }
            }
        }
    }

    grid_sync();

    // ================= Phase E: weighted combine ===============================
    {
        int gw = (cta * 256 + tid) >> 5;       // global warp id, 0..1183
        int c = (tid & 31) * 4;
        for (int b = gw; b < BB; b += GRID * 8) {
            float4 r = make_float4(0.f, 0.f, 0.f, 0.f);
#pragma unroll
            for (int j = 0; j < 3; j++) {
                float w = g_w[b * 3 + j];
                int   p = g_pos[b * 3 + j];
                float4 sv = *(const float4*)(g_scratch + (size_t)p * DD + c);
                r.x += w * sv.x;
                r.y += w * sv.y;
                r.z += w * sv.z;
                r.w += w * sv.w;
            }
            *(float4*)(out + (size_t)b * DD + c) = r;
        }
    }
}

// ---------------- launch ------------------------------------------------------
extern "C" void kernel_launch(void* const* d_in, const int* in_sizes, int n_in,
                              void* d_out, int out_size) {
    const float* x    = (const float*)d_in[0];
    const float* dsc  = (const float*)d_in[1];
    const float* cent = (const float*)d_in[2];
    const float* W    = (const float*)d_in[3];
    const float* bias = (const float*)d_in[4];
    float* out = (float*)d_out;

    cudaFuncSetAttribute(fused, cudaFuncAttributeMaxDynamicSharedMemorySize,
                         FUSED_SMEM);
    fused<<<GRID, 256, FUSED_SMEM>>>(x, dsc, cent, W, bias, out);
}

// round 12
// speedup vs baseline: 1.2841x; 1.1503x over previous
#include <cuda_runtime.h>
#include <cstdint>

#define BB 16384
#define EE 64
#define DD 128
#define ES 3
#define NBLK (BB / 64)          // 256 route blocks
#define GRID 148
#define NT 512

typedef unsigned long long ull;

// ---------------- device scratch (static; no allocations allowed) -------------
__device__ int    g_offsets[EE + 1];
__device__ int    g_ntiles;
__device__ int    g_picked[BB * ES];
__device__ int    g_loc[BB * ES];
__device__ float  g_w[BB * ES];
__device__ int    g_entry_token[BB * ES];
__device__ int    g_pos[BB * ES];
__device__ int2   g_tiles[1024];
__device__ int    g_blockhist[NBLK * EE];
__device__ int    g_blockbase[NBLK * EE];
__device__ float  g_wt[(size_t)EE * DD * DD];        // tf32-rounded W^T [e][o][k]
__device__ float  g_scratch[(size_t)BB * ES * DD];   // 25 MB

// ---------------- grid barrier (sense-reversing, replay-safe) ------------------
__device__ int          g_bar_count = 0;
__device__ volatile int g_bar_gen   = 0;

__device__ __forceinline__ void grid_sync() {
    __syncthreads();
    if (threadIdx.x == 0) {
        __threadfence();
        int gen = g_bar_gen;
        if (atomicAdd(&g_bar_count, 1) == GRID - 1) {
            g_bar_count = 0;
            __threadfence();
            g_bar_gen = gen + 1;
        } else {
            while (g_bar_gen == gen) __nanosleep(64);
        }
        __threadfence();
    }
    __syncthreads();
}

// ---------------- helpers ------------------------------------------------------
__device__ __forceinline__ ull pack2(float lo, float hi) {
    ull r;
    asm("mov.b64 %0, {%1, %2};" : "=l"(r) : "f"(lo), "f"(hi));
    return r;
}
__device__ __forceinline__ float2 unpack2(ull v) {
    float2 f;
    asm("mov.b64 {%0, %1}, %2;" : "=f"(f.x), "=f"(f.y) : "l"(v));
    return f;
}
__device__ __forceinline__ ull fma2(ull a, ull b, ull c) {
    ull d;
    asm("fma.rn.f32x2 %0, %1, %2, %3;" : "=l"(d) : "l"(a), "l"(b), "l"(c));
    return d;
}
__device__ __forceinline__ ull add2(ull a, ull b) {
    ull d;
    asm("add.rn.f32x2 %0, %1, %2;" : "=l"(d) : "l"(a), "l"(b));
    return d;
}
__device__ __forceinline__ float to_tf32(float x) {
    float r;
    asm("cvt.rna.tf32.f32 %0, %1;" : "=f"(r) : "f"(x));
    return r;
}
__device__ __forceinline__ void mma_tf32(float* c, const uint32_t* a,
                                         const uint32_t* b) {
    asm volatile(
        "mma.sync.aligned.m16n8k8.row.col.f32.tf32.tf32.f32 "
        "{%0,%1,%2,%3}, {%4,%5,%6,%7}, {%8,%9}, {%0,%1,%2,%3};"
        : "+f"(c[0]), "+f"(c[1]), "+f"(c[2]), "+f"(c[3])
        : "r"(a[0]), "r"(a[1]), "r"(a[2]), "r"(a[3]), "r"(b[0]), "r"(b[1]));
}
__device__ __forceinline__ void cp_async16(uint32_t dst, const void* src,
                                           uint32_t sz) {
    asm volatile("cp.async.cg.shared.global [%0], [%1], 16, %2;"
                 :: "r"(dst), "l"(src), "r"(sz) : "memory");
}
#define CP_COMMIT() asm volatile("cp.async.commit_group;" ::: "memory")
#define CP_WAIT0()  asm volatile("cp.async.wait_group 0;" ::: "memory")

// smem layout sizes
#define K1_XP 68
#define K1_CP 36
#define K1_TP 36
#define HALF_F (128 * K1_XP + 128 * K1_CP + 64 * K1_TP + 64 + 64)  // 15744 floats
#define K4_LD 132
#define FUSED_SMEM (2 * 128 * K4_LD * 4)    // 135168 B

// ---------------- fused persistent kernel --------------------------------------
__global__ __launch_bounds__(NT) void fused(const float* __restrict__ x,
                                            const float* __restrict__ dscale,
                                            const float* __restrict__ cent,
                                            const float* __restrict__ W,
                                            const float* __restrict__ bias,
                                            float* __restrict__ out) {
    extern __shared__ float sm[];
    int tid = threadIdx.x;
    int cta = blockIdx.x;

    // ================= Phase A1: CTAs 0..63 build tf32 W^T ====================
    if (cta < EE) {
        float* wsm = sm;                         // [128][132] wsm[k][o]
        const float4* w4 = (const float4*)(W + (size_t)cta * DD * DD);
#pragma unroll
        for (int i = 0; i < 8; i++) {
            int idx = i * NT + tid;
            float4 v = __ldg(w4 + idx);
            *(float4*)(wsm + (idx >> 5) * 132 + (idx & 31) * 4) = v;
        }
        __syncthreads();
        float4* dst = (float4*)(g_wt + (size_t)cta * DD * DD);
#pragma unroll
        for (int i = 0; i < 8; i++) {
            int idx = i * NT + tid;
            int o = idx >> 5, kq = idx & 31;
            float4 v;
            v.x = to_tf32(wsm[(kq * 4 + 0) * 132 + o]);
            v.y = to_tf32(wsm[(kq * 4 + 1) * 132 + o]);
            v.z = to_tf32(wsm[(kq * 4 + 2) * 132 + o]);
            v.w = to_tf32(wsm[(kq * 4 + 3) * 132 + o]);
            dst[o * 32 + kq] = v;
        }
        __syncthreads();
    }

    // ================= Phase A2: routing, 2 blocks per CTA ====================
    {
        int half = tid >> 8, rtid = tid & 255;
        int blk  = half * GRID + cta;
        bool act = blk < NBLK;
        float*  xs   = sm + half * HALF_F;          // [128][K1_XP]
        float*  cs   = xs + 128 * K1_XP;            // [128][K1_CP]
        float*  ts   = cs + 128 * K1_CP;            // [64][K1_TP]
        double* nc2s = (double*)(ts + 64 * K1_TP);  // [32]
        int*    hist = (int*)(nc2s + 32);           // [64]
        const float4* x4 = (const float4*)x;
        const float4* c4 = (const float4*)cent;
        int t0 = blk * 64;

        if (act && rtid < 64) hist[rtid] = 0;
        if (act) {
#pragma unroll
            for (int i = 0; i < 8; i++) {
                int f = i * 256 + rtid;
                int tr = f & 63, kc = f >> 6;
                float4 v = __ldg(x4 + (size_t)(t0 + tr) * 32 + kc);
                xs[(kc * 4 + 0) * K1_XP + tr] = v.x;
                xs[(kc * 4 + 1) * K1_XP + tr] = v.y;
                xs[(kc * 4 + 2) * K1_XP + tr] = v.z;
                xs[(kc * 4 + 3) * K1_XP + tr] = v.w;
            }
#pragma unroll
            for (int i = 0; i < 4; i++) {
                int f = i * 256 + rtid;
                int er = f & 31, kc = f >> 5;
                float4 v = __ldg(c4 + (size_t)er * 32 + kc);
                cs[(kc * 4 + 0) * K1_CP + er] = v.x;
                cs[(kc * 4 + 1) * K1_CP + er] = v.y;
                cs[(kc * 4 + 2) * K1_CP + er] = v.z;
                cs[(kc * 4 + 3) * K1_CP + er] = v.w;
            }
        }
        __syncthreads();

        if (act && rtid < 32) {
            double a0 = 0.0, a1 = 0.0;
#pragma unroll 8
            for (int k = 0; k < 128; k += 2) {
                double u0 = (double)cs[(k + 0) * K1_CP + rtid]; a0 = fma(u0, u0, a0);
                double u1 = (double)cs[(k + 1) * K1_CP + rtid]; a1 = fma(u1, u1, a1);
            }
            nc2s[rtid] = a0 + a1;
        }

        if (act) {
            int tx = rtid & 7, ty = rtid >> 3;
            ull acc[2][2][4];
#pragma unroll
            for (int i = 0; i < 2; i++)
#pragma unroll
                for (int j = 0; j < 2; j++)
#pragma unroll
                    for (int s = 0; s < 4; s++) acc[i][j][s] = 0ULL;

            const float* ap = xs + ty * 2;
            const float* bp = cs + tx * 4;
#pragma unroll 4
            for (int k = 0; k < 128; k += 4) {
#pragma unroll
                for (int s = 0; s < 4; s++) {
                    float2  a  = *(const float2*)(ap + (k + s) * K1_XP);
                    double2 nb = *(const double2*)(bp + (k + s) * K1_CP);
                    ull b01 = __double_as_longlong(nb.x);
                    ull b23 = __double_as_longlong(nb.y);
                    ull a0 = pack2(a.x, a.x), a1 = pack2(a.y, a.y);
                    acc[0][0][s] = fma2(a0, b01, acc[0][0][s]);
                    acc[0][1][s] = fma2(a0, b23, acc[0][1][s]);
                    acc[1][0][s] = fma2(a1, b01, acc[1][0][s]);
                    acc[1][1][s] = fma2(a1, b23, acc[1][1][s]);
                }
            }
#pragma unroll
            for (int i = 0; i < 2; i++) {
                ull s01 = add2(add2(acc[i][0][0], acc[i][0][1]),
                               add2(acc[i][0][2], acc[i][0][3]));
                ull s23 = add2(add2(acc[i][1][0], acc[i][1][1]),
                               add2(acc[i][1][2], acc[i][1][3]));
                float2 v01 = unpack2(s01), v23 = unpack2(s23);
                int tok = ty * 2 + i;
                *(float4*)(ts + tok * K1_TP + tx * 4) =
                    make_float4(v01.x, v01.y, v23.x, v23.y);
            }
        }
        __syncthreads();

        // fp64 pass: 2 threads per token (experts 0-31 / 32-63)
        if (act && rtid < 128) {
            int tok = rtid >> 1, side = rtid & 1;
            double a0 = 0.0, a1 = 0.0, a2 = 0.0, a3 = 0.0;
#pragma unroll 8
            for (int k = 0; k < 128; k += 4) {
                double u0 = (double)xs[(k + 0) * K1_XP + tok]; a0 = fma(u0, u0, a0);
                double u1 = (double)xs[(k + 1) * K1_XP + tok]; a1 = fma(u1, u1, a1);
                double u2 = (double)xs[(k + 2) * K1_XP + tok]; a2 = fma(u2, u2, a2);
                double u3 = (double)xs[(k + 3) * K1_XP + tok]; a3 = fma(u3, u3, a3);
            }
            double nx2 = (a0 + a1) + (a2 + a3);

            float  s  = __ldg(dscale);
            double Kd = ((double)s * (double)s) * (1.0 / 128.0);

            double av[3] = {1e300, 1e300, 1e300};
            int    ai[3] = {0, 0, 0};
            for (int ei = 0; ei < 32; ei++) {
                double t  = (double)ts[tok * K1_TP + ei];
                double br = nx2 + nc2s[ei];
                double dd = Kd * (side == 0 ? fma(-2.0, t, br) : fma(2.0, t, br));
                int e = side * 32 + ei;
                if (dd < av[0]) {
                    av[2] = av[1]; ai[2] = ai[1];
                    av[1] = av[0]; ai[1] = ai[0];
                    av[0] = dd;    ai[0] = e;
                } else if (dd < av[1]) {
                    av[2] = av[1]; ai[2] = ai[1];
                    av[1] = dd;    ai[1] = e;
                } else if (dd < av[2]) {
                    av[2] = dd;    ai[2] = e;
                }
            }
            // fetch partner (side 1) candidates
            double bv[3];
            int    bi[3];
#pragma unroll
            for (int r = 0; r < 3; r++) {
                bv[r] = __shfl_down_sync(0xFFFFFFFFu, av[r], 1);
                bi[r] = __shfl_down_sync(0xFFFFFFFFu, ai[r], 1);
            }
            if (side == 0) {
                // merge (strict < : side-1 wins only if strictly smaller)
                int ri[3]; int pa = 0, pb = 0;
#pragma unroll
                for (int r = 0; r < 3; r++) {
                    bool takeB = (pa > 2) || (pb <= 2 && bv[pb] < av[pa]);
                    if (takeB) { ri[r] = bi[pb]; pb++; }
                    else       { ri[r] = ai[pa]; pa++; }
                }
                float d0 = (float)(Kd * fma(-2.0, (double)ts[tok * K1_TP + 0], nx2 + nc2s[0]));
                float d1 = (float)(Kd * fma(-2.0, (double)ts[tok * K1_TP + 1], nx2 + nc2s[1]));
                float d2 = (float)(Kd * fma(-2.0, (double)ts[tok * K1_TP + 2], nx2 + nc2s[2]));
                float w0 = 1.0f / (1.0f + d0);
                float w1 = 1.0f / (1.0f + d1);
                float w2 = 1.0f / (1.0f + d2);
                float z  = w0 + w1 + w2;
                int b = t0 + tok;
                g_picked[b * 3 + 0] = ri[0];
                g_picked[b * 3 + 1] = ri[1];
                g_picked[b * 3 + 2] = ri[2];
                g_w[b * 3 + 0] = w0 / z;
                g_w[b * 3 + 1] = w1 / z;
                g_w[b * 3 + 2] = w2 / z;
                g_loc[b * 3 + 0] = atomicAdd(&hist[ri[0]], 1);
                g_loc[b * 3 + 1] = atomicAdd(&hist[ri[1]], 1);
                g_loc[b * 3 + 2] = atomicAdd(&hist[ri[2]], 1);
            }
        }
        __syncthreads();
        if (act && rtid < 64) g_blockhist[blk * 64 + rtid] = hist[rtid];
    }

    grid_sync();

    // ================= Phase B: scan (CTA 0, first 256 threads) ===============
    if (cta == 0) {
        int* csum = (int*)sm;        // [256]
        int* cnts = csum + 256;      // [64]
        int* off  = cnts + 64;       // [65]
        int* toff = off + 65;        // [64]
        int e = tid & 63, c = (tid >> 6) & 3;

        if (tid < 256) {
            int s = 0;
#pragma unroll 8
            for (int i = 0; i < 64; i++) s += g_blockhist[((c << 6) + i) * 64 + e];
            csum[c * 64 + e] = s;
        }
        __syncthreads();

        if (tid < 64) {
            int t0 = csum[0 * 64 + tid], t1 = csum[1 * 64 + tid];
            int t2 = csum[2 * 64 + tid], t3 = csum[3 * 64 + tid];
            cnts[tid] = t0 + t1 + t2 + t3;
            csum[0 * 64 + tid] = 0;
            csum[1 * 64 + tid] = t0;
            csum[2 * 64 + tid] = t0 + t1;
            csum[3 * 64 + tid] = t0 + t1 + t2;
        }
        __syncthreads();

        if (tid == 0) {
            int o = 0, to = 0;
            for (int i = 0; i < 64; i++) {
                off[i] = o; toff[i] = to;
                o += cnts[i]; to += (cnts[i] + 127) >> 7;
            }
            off[64] = o; g_ntiles = to;
        }
        __syncthreads();

        if (tid < 64) {
            g_offsets[tid] = off[tid];
            int nt = (cnts[tid] + 127) >> 7;
            for (int i = 0; i < nt; i++)
                g_tiles[toff[tid] + i] = make_int2(tid, off[tid] + (i << 7));
        }
        if (tid == 0) g_offsets[64] = off[64];
        __syncthreads();

        if (tid < 256) {
            int run = off[e] + csum[c * 64 + e];
            for (int i = 0; i < 64; i++) {
                int idx = ((c << 6) + i) * 64 + e;
                int v = g_blockhist[idx];
                g_blockbase[idx] = run;
                run += v;
            }
        }
    }

    grid_sync();

    // ================= Phase C: scatter ========================================
    {
        int t = cta * NT + tid;
        if (t < BB) {
            int blk = t >> 6;
#pragma unroll
            for (int j = 0; j < 3; j++) {
                int e = g_picked[t * 3 + j];
                int p = g_blockbase[blk * 64 + e] + g_loc[t * 3 + j];
                g_entry_token[p] = t;
                g_pos[t * 3 + j] = p;
            }
        }
    }

    grid_sync();

    // ================= Phase D: TF32 grouped GEMM (16 warps) ===================
    {
        float* As = sm;                  // [128][K4_LD]
        float* Bs = sm + 128 * K4_LD;    // [128][K4_LD]
        uint32_t sb = (uint32_t)__cvta_generic_to_shared(sm);
        uint32_t bsb = sb + 128 * K4_LD * 4;
        int ntiles = g_ntiles;
        const float4* x4 = (const float4*)x;

        for (int t = cta; t < ntiles; t += GRID) {
            int2 tl = g_tiles[t];
            int e = tl.x, rs = tl.y;
            int rows = g_offsets[e + 1] - rs;
            if (rows > 128) rows = 128;

            __syncthreads();   // prior smem readers done

            // B: cp.async verbatim copy of pre-rounded W^T
            const float4* wt4 = (const float4*)(g_wt + (size_t)e * DD * DD);
#pragma unroll
            for (int i = 0; i < 8; i++) {
                int idx = i * NT + tid;
                int o = idx >> 5, kq = idx & 31;
                cp_async16(bsb + (o * K4_LD + kq * 4) * 4, wt4 + idx, 16);
            }
            CP_COMMIT();

            // A: gather + tf32 round + STS (4 threads per row)
            {
                int tr = tid >> 2, h = tid & 3;
                bool valid = tr < rows;
                int tok = valid ? g_entry_token[rs + tr] : 0;
                const float4* xr = x4 + (size_t)tok * 32;
#pragma unroll
                for (int i = 0; i < 8; i++) {
                    int kc = h * 8 + i;
                    float4 v = make_float4(0.f, 0.f, 0.f, 0.f);
                    if (valid) v = __ldg(xr + kc);
                    v.x = to_tf32(v.x); v.y = to_tf32(v.y);
                    v.z = to_tf32(v.z); v.w = to_tf32(v.w);
                    *(float4*)(As + tr * K4_LD + kc * 4) = v;
                }
            }
            CP_WAIT0();
            __syncthreads();

            int wid = tid >> 5, lane = tid & 31;
            int gid = lane >> 2, tig = lane & 3;
            int m0 = (wid & 3) * 32, n0 = (wid >> 2) * 32;

            float acc[2][4][4];
#pragma unroll
            for (int i = 0; i < 2; i++)
#pragma unroll
                for (int j = 0; j < 4; j++)
#pragma unroll
                    for (int r = 0; r < 4; r++) acc[i][j][r] = 0.f;

            const float* arow = As + (m0 + gid) * K4_LD + tig;
            const float* brow = Bs + (n0 + gid) * K4_LD + tig;

#pragma unroll 4
            for (int kb = 0; kb < 128; kb += 8) {
                uint32_t a[2][4];
#pragma unroll
                for (int i = 0; i < 2; i++) {
                    const float* p = arow + i * 16 * K4_LD + kb;
                    a[i][0] = __float_as_uint(p[0]);
                    a[i][1] = __float_as_uint(p[8 * K4_LD]);
                    a[i][2] = __float_as_uint(p[4]);
                    a[i][3] = __float_as_uint(p[8 * K4_LD + 4]);
                }
                uint32_t b[4][2];
#pragma unroll
                for (int j = 0; j < 4; j++) {
                    const float* p = brow + j * 8 * K4_LD + kb;
                    b[j][0] = __float_as_uint(p[0]);
                    b[j][1] = __float_as_uint(p[4]);
                }
#pragma unroll
                for (int i = 0; i < 2; i++)
#pragma unroll
                    for (int j = 0; j < 4; j++)
                        mma_tf32(acc[i][j], a[i], b[j]);
            }

            const float* be = bias + (size_t)e * DD;
#pragma unroll
            for (int i = 0; i < 2; i++) {
                int r0 = m0 + i * 16 + gid;
                int r1 = r0 + 8;
                bool v0 = r0 < rows, v1 = r1 < rows;
                float* o0 = g_scratch + (size_t)(rs + r0) * DD;
                float* o1 = g_scratch + (size_t)(rs + r1) * DD;
#pragma unroll
                for (int j = 0; j < 4; j++) {
                    int col = n0 + j * 8 + tig * 2;
                    float2 bv = *(const float2*)(be + col);
                    if (v0) *(float2*)(o0 + col) =
                        make_float2(acc[i][j][0] + bv.x, acc[i][j][1] + bv.y);
                    if (v1) *(float2*)(o1 + col) =
                        make_float2(acc[i][j][2] + bv.x, acc[i][j][3] + bv.y);
                }
            }
        }
    }

    grid_sync();

    // ================= Phase E: weighted combine ===============================
    {
        int gw = (cta * NT + tid) >> 5;        // global warp id, 0..2367
        int c = (tid & 31) * 4;
        for (int b = gw; b < BB; b += GRID * 16) {
            float4 r = make_float4(0.f, 0.f, 0.f, 0.f);
#pragma unroll
            for (int j = 0; j < 3; j++) {
                float w = g_w[b * 3 + j];
                int   p = g_pos[b * 3 + j];
                float4 sv = *(const float4*)(g_scratch + (size_t)p * DD + c);
                r.x += w * sv.x;
                r.y += w * sv.y;
                r.z += w * sv.z;
                r.w += w * sv.w;
            }
            *(float4*)(out + (size_t)b * DD + c) = r;
        }
    }
}

// ---------------- launch ------------------------------------------------------
extern "C" void kernel_launch(void* const* d_in, const int* in_sizes, int n_in,
                              void* d_out, int out_size) {
    const float* x    = (const float*)d_in[0];
    const float* dsc  = (const float*)d_in[1];
    const float* cent = (const float*)d_in[2];
    const float* W    = (const float*)d_in[3];
    const float* bias = (const float*)d_in[4];
    float* out = (float*)d_out;

    cudaFuncSetAttribute(fused, cudaFuncAttributeMaxDynamicSharedMemorySize,
                         FUSED_SMEM);
    fused<<<GRID, NT, FUSED_SMEM>>>(x, dsc, cent, W, bias, out);
}

// round 13
// speedup vs baseline: 1.3310x; 1.0365x over previous
#include <cuda_runtime.h>
#include <cstdint>

#define BB 16384
#define EE 64
#define DD 128
#define ES 3
#define NBLK (BB / 64)          // 256 route blocks
#define GRID 296                // 2 CTAs/SM x 148 SMs, all co-resident
#define NT 512

typedef unsigned long long ull;

// ---------------- device scratch (static; no allocations allowed) -------------
__device__ int    g_offsets[EE + 1];
__device__ int    g_ntiles;
__device__ int    g_picked[BB * ES];
__device__ int    g_loc[BB * ES];
__device__ float  g_w[BB * ES];
__device__ int    g_entry_token[BB * ES];
__device__ int    g_pos[BB * ES];
__device__ int2   g_tiles[1024];
__device__ int    g_blockhist[NBLK * EE];
__device__ int    g_blockbase[NBLK * EE];
__device__ float  g_wt[(size_t)EE * DD * DD];        // tf32-rounded W^T [e][o][k]
__device__ float  g_scratch[(size_t)BB * ES * DD];   // 25 MB

// ---------------- grid barrier (sense-reversing, replay-safe) ------------------
__device__ int          g_bar_count = 0;
__device__ volatile int g_bar_gen   = 0;

__device__ __forceinline__ void grid_sync() {
    __syncthreads();
    if (threadIdx.x == 0) {
        __threadfence();
        int gen = g_bar_gen;
        if (atomicAdd(&g_bar_count, 1) == GRID - 1) {
            g_bar_count = 0;
            __threadfence();
            g_bar_gen = gen + 1;
        } else {
            while (g_bar_gen == gen) __nanosleep(32);
        }
        __threadfence();
    }
    __syncthreads();
}

// ---------------- helpers ------------------------------------------------------
__device__ __forceinline__ ull pack2(float lo, float hi) {
    ull r;
    asm("mov.b64 %0, {%1, %2};" : "=l"(r) : "f"(lo), "f"(hi));
    return r;
}
__device__ __forceinline__ float2 unpack2(ull v) {
    float2 f;
    asm("mov.b64 {%0, %1}, %2;" : "=f"(f.x), "=f"(f.y) : "l"(v));
    return f;
}
__device__ __forceinline__ ull fma2(ull a, ull b, ull c) {
    ull d;
    asm("fma.rn.f32x2 %0, %1, %2, %3;" : "=l"(d) : "l"(a), "l"(b), "l"(c));
    return d;
}
__device__ __forceinline__ ull add2(ull a, ull b) {
    ull d;
    asm("add.rn.f32x2 %0, %1, %2;" : "=l"(d) : "l"(a), "l"(b));
    return d;
}
__device__ __forceinline__ float to_tf32(float x) {
    float r;
    asm("cvt.rna.tf32.f32 %0, %1;" : "=f"(r) : "f"(x));
    return r;
}
__device__ __forceinline__ void mma_tf32(float* c, const uint32_t* a,
                                         const uint32_t* b) {
    asm volatile(
        "mma.sync.aligned.m16n8k8.row.col.f32.tf32.tf32.f32 "
        "{%0,%1,%2,%3}, {%4,%5,%6,%7}, {%8,%9}, {%0,%1,%2,%3};"
        : "+f"(c[0]), "+f"(c[1]), "+f"(c[2]), "+f"(c[3])
        : "r"(a[0]), "r"(a[1]), "r"(a[2]), "r"(a[3]), "r"(b[0]), "r"(b[1]));
}
__device__ __forceinline__ void cp_async16(uint32_t dst, const void* src) {
    asm volatile("cp.async.cg.shared.global [%0], [%1], 16;"
                 :: "r"(dst), "l"(src) : "memory");
}
#define CP_COMMIT() asm volatile("cp.async.commit_group;" ::: "memory")
#define CP_WAIT0()  asm volatile("cp.async.wait_group 0;" ::: "memory")

// smem layout sizes
#define K1_XP 68
#define K1_CP 36
#define K1_TP 36
#define K4_LD 132
// GEMM: A[64][132] + B[128][132] = 101376 B (dominates routing's 62976 B)
#define FUSED_SMEM ((64 * K4_LD + 128 * K4_LD) * 4 + 128)

// ---------------- fused persistent kernel --------------------------------------
__global__ __launch_bounds__(NT, 2) void fused(const float* __restrict__ x,
                                               const float* __restrict__ dscale,
                                               const float* __restrict__ cent,
                                               const float* __restrict__ W,
                                               const float* __restrict__ bias,
                                               float* __restrict__ out) {
    extern __shared__ float sm[];
    int tid = threadIdx.x;
    int cta = blockIdx.x;

    if (cta < NBLK) {
        // ============== Phase A (routing CTAs): one route block ===============
        float*  xs   = sm;                          // [128][K1_XP]
        float*  cs   = xs + 128 * K1_XP;            // [128][K1_CP]
        float*  ts   = cs + 128 * K1_CP;            // [64][K1_TP]
        double* nc2s = (double*)(ts + 64 * K1_TP);  // [32]
        int*    hist = (int*)(nc2s + 32);           // [64]
        const float4* x4 = (const float4*)x;
        const float4* c4 = (const float4*)cent;
        int t0 = cta * 64;

        if (tid < 64) hist[tid] = 0;
#pragma unroll
        for (int i = 0; i < 4; i++) {               // x tile: 2048 float4
            int f = i * NT + tid;
            int tr = f & 63, kc = f >> 6;
            float4 v = __ldg(x4 + (size_t)(t0 + tr) * 32 + kc);
            xs[(kc * 4 + 0) * K1_XP + tr] = v.x;
            xs[(kc * 4 + 1) * K1_XP + tr] = v.y;
            xs[(kc * 4 + 2) * K1_XP + tr] = v.z;
            xs[(kc * 4 + 3) * K1_XP + tr] = v.w;
        }
#pragma unroll
        for (int i = 0; i < 2; i++) {               // centroids: 1024 float4
            int f = i * NT + tid;
            int er = f & 31, kc = f >> 5;
            float4 v = __ldg(c4 + (size_t)er * 32 + kc);
            cs[(kc * 4 + 0) * K1_CP + er] = v.x;
            cs[(kc * 4 + 1) * K1_CP + er] = v.y;
            cs[(kc * 4 + 2) * K1_CP + er] = v.z;
            cs[(kc * 4 + 3) * K1_CP + er] = v.w;
        }
        __syncthreads();

        if (tid < 32) {
            double a0 = 0.0, a1 = 0.0;
#pragma unroll 8
            for (int k = 0; k < 128; k += 2) {
                double u0 = (double)cs[(k + 0) * K1_CP + tid]; a0 = fma(u0, u0, a0);
                double u1 = (double)cs[(k + 1) * K1_CP + tid]; a1 = fma(u1, u1, a1);
            }
            nc2s[tid] = a0 + a1;
        }

        if (tid < 256) {     // dots: EXACT same per-thread mapping as before
            int tx = tid & 7, ty = tid >> 3;
            ull acc[2][2][4];
#pragma unroll
            for (int i = 0; i < 2; i++)
#pragma unroll
                for (int j = 0; j < 2; j++)
#pragma unroll
                    for (int s = 0; s < 4; s++) acc[i][j][s] = 0ULL;

            const float* ap = xs + ty * 2;
            const float* bp = cs + tx * 4;
#pragma unroll 4
            for (int k = 0; k < 128; k += 4) {
#pragma unroll
                for (int s = 0; s < 4; s++) {
                    float2  a  = *(const float2*)(ap + (k + s) * K1_XP);
                    double2 nb = *(const double2*)(bp + (k + s) * K1_CP);
                    ull b01 = __double_as_longlong(nb.x);
                    ull b23 = __double_as_longlong(nb.y);
                    ull a0 = pack2(a.x, a.x), a1 = pack2(a.y, a.y);
                    acc[0][0][s] = fma2(a0, b01, acc[0][0][s]);
                    acc[0][1][s] = fma2(a0, b23, acc[0][1][s]);
                    acc[1][0][s] = fma2(a1, b01, acc[1][0][s]);
                    acc[1][1][s] = fma2(a1, b23, acc[1][1][s]);
                }
            }
#pragma unroll
            for (int i = 0; i < 2; i++) {
                ull s01 = add2(add2(acc[i][0][0], acc[i][0][1]),
                               add2(acc[i][0][2], acc[i][0][3]));
                ull s23 = add2(add2(acc[i][1][0], acc[i][1][1]),
                               add2(acc[i][1][2], acc[i][1][3]));
                float2 v01 = unpack2(s01), v23 = unpack2(s23);
                int tok = ty * 2 + i;
                *(float4*)(ts + tok * K1_TP + tx * 4) =
                    make_float4(v01.x, v01.y, v23.x, v23.y);
            }
        }
        __syncthreads();

        // fp64 pass: 2 threads per token (experts 0-31 / 32-63) — unchanged
        if (tid < 128) {
            int tok = tid >> 1, side = tid & 1;
            double a0 = 0.0, a1 = 0.0, a2 = 0.0, a3 = 0.0;
#pragma unroll 8
            for (int k = 0; k < 128; k += 4) {
                double u0 = (double)xs[(k + 0) * K1_XP + tok]; a0 = fma(u0, u0, a0);
                double u1 = (double)xs[(k + 1) * K1_XP + tok]; a1 = fma(u1, u1, a1);
                double u2 = (double)xs[(k + 2) * K1_XP + tok]; a2 = fma(u2, u2, a2);
                double u3 = (double)xs[(k + 3) * K1_XP + tok]; a3 = fma(u3, u3, a3);
            }
            double nx2 = (a0 + a1) + (a2 + a3);

            float  s  = __ldg(dscale);
            double Kd = ((double)s * (double)s) * (1.0 / 128.0);

            double av[3] = {1e300, 1e300, 1e300};
            int    ai[3] = {0, 0, 0};
            for (int ei = 0; ei < 32; ei++) {
                double t  = (double)ts[tok * K1_TP + ei];
                double br = nx2 + nc2s[ei];
                double dd = Kd * (side == 0 ? fma(-2.0, t, br) : fma(2.0, t, br));
                int e = side * 32 + ei;
                if (dd < av[0]) {
                    av[2] = av[1]; ai[2] = ai[1];
                    av[1] = av[0]; ai[1] = ai[0];
                    av[0] = dd;    ai[0] = e;
                } else if (dd < av[1]) {
                    av[2] = av[1]; ai[2] = ai[1];
                    av[1] = dd;    ai[1] = e;
                } else if (dd < av[2]) {
                    av[2] = dd;    ai[2] = e;
                }
            }
            double bv[3];
            int    bi[3];
#pragma unroll
            for (int r = 0; r < 3; r++) {
                bv[r] = __shfl_down_sync(0xFFFFFFFFu, av[r], 1);
                bi[r] = __shfl_down_sync(0xFFFFFFFFu, ai[r], 1);
            }
            if (side == 0) {
                int ri[3]; int pa = 0, pb = 0;
#pragma unroll
                for (int r = 0; r < 3; r++) {
                    bool takeB = (pa > 2) || (pb <= 2 && bv[pb] < av[pa]);
                    if (takeB) { ri[r] = bi[pb]; pb++; }
                    else       { ri[r] = ai[pa]; pa++; }
                }
                float d0 = (float)(Kd * fma(-2.0, (double)ts[tok * K1_TP + 0], nx2 + nc2s[0]));
                float d1 = (float)(Kd * fma(-2.0, (double)ts[tok * K1_TP + 1], nx2 + nc2s[1]));
                float d2 = (float)(Kd * fma(-2.0, (double)ts[tok * K1_TP + 2], nx2 + nc2s[2]));
                float w0 = 1.0f / (1.0f + d0);
                float w1 = 1.0f / (1.0f + d1);
                float w2 = 1.0f / (1.0f + d2);
                float z  = w0 + w1 + w2;
                int b = t0 + tok;
                g_picked[b * 3 + 0] = ri[0];
                g_picked[b * 3 + 1] = ri[1];
                g_picked[b * 3 + 2] = ri[2];
                g_w[b * 3 + 0] = w0 / z;
                g_w[b * 3 + 1] = w1 / z;
                g_w[b * 3 + 2] = w2 / z;
                g_loc[b * 3 + 0] = atomicAdd(&hist[ri[0]], 1);
                g_loc[b * 3 + 1] = atomicAdd(&hist[ri[1]], 1);
                g_loc[b * 3 + 2] = atomicAdd(&hist[ri[2]], 1);
            }
        }
        __syncthreads();
        if (tid < 64) g_blockhist[cta * 64 + tid] = hist[tid];
    } else {
        // ============== Phase A (CTAs 256..295): build tf32 W^T ===============
        float* wsm = sm;                             // [128][132] wsm[k][o]
        for (int e = cta - NBLK; e < EE; e += GRID - NBLK) {
            const float4* w4 = (const float4*)(W + (size_t)e * DD * DD);
            __syncthreads();
#pragma unroll
            for (int i = 0; i < 8; i++) {
                int idx = i * NT + tid;
                float4 v = __ldg(w4 + idx);
                *(float4*)(wsm + (idx >> 5) * 132 + (idx & 31) * 4) = v;
            }
            __syncthreads();
            float4* dst = (float4*)(g_wt + (size_t)e * DD * DD);
#pragma unroll
            for (int i = 0; i < 8; i++) {
                int idx = i * NT + tid;
                int o = idx >> 5, kq = idx & 31;
                float4 v;
                v.x = to_tf32(wsm[(kq * 4 + 0) * 132 + o]);
                v.y = to_tf32(wsm[(kq * 4 + 1) * 132 + o]);
                v.z = to_tf32(wsm[(kq * 4 + 2) * 132 + o]);
                v.w = to_tf32(wsm[(kq * 4 + 3) * 132 + o]);
                dst[o * 32 + kq] = v;
            }
        }
    }

    grid_sync();

    // ================= Phase B: scan (CTA 0) ===================================
    if (cta == 0) {
        int* csum = (int*)sm;        // [256]
        int* cnts = csum + 256;      // [64]
        int* off  = cnts + 64;       // [65]
        int* toff = off + 65;        // [64]
        int e = tid & 63, c = (tid >> 6) & 3;

        if (tid < 256) {
            int s = 0;
#pragma unroll 8
            for (int i = 0; i < 64; i++) s += g_blockhist[((c << 6) + i) * 64 + e];
            csum[c * 64 + e] = s;
        }
        __syncthreads();

        if (tid < 64) {
            int t0 = csum[0 * 64 + tid], t1 = csum[1 * 64 + tid];
            int t2 = csum[2 * 64 + tid], t3 = csum[3 * 64 + tid];
            cnts[tid] = t0 + t1 + t2 + t3;
            csum[0 * 64 + tid] = 0;
            csum[1 * 64 + tid] = t0;
            csum[2 * 64 + tid] = t0 + t1;
            csum[3 * 64 + tid] = t0 + t1 + t2;
        }
        __syncthreads();

        if (tid == 0) {
            int o = 0, to = 0;
            for (int i = 0; i < 64; i++) {
                off[i] = o; toff[i] = to;
                o += cnts[i]; to += (cnts[i] + 63) >> 6;
            }
            off[64] = o; g_ntiles = to;
        }
        __syncthreads();

        if (tid < 64) {
            g_offsets[tid] = off[tid];
            int nt = (cnts[tid] + 63) >> 6;
            for (int i = 0; i < nt; i++)
                g_tiles[toff[tid] + i] = make_int2(tid, off[tid] + (i << 6));
        }
        if (tid == 0) g_offsets[64] = off[64];
        __syncthreads();

        if (tid < 256) {
            int run = off[e] + csum[c * 64 + e];
            for (int i = 0; i < 64; i++) {
                int idx = ((c << 6) + i) * 64 + e;
                int v = g_blockhist[idx];
                g_blockbase[idx] = run;
                run += v;
            }
        }
    }

    grid_sync();

    // ================= Phase C: scatter ========================================
    {
        int t = cta * NT + tid;
        if (t < BB) {
            int blk = t >> 6;
#pragma unroll
            for (int j = 0; j < 3; j++) {
                int e = g_picked[t * 3 + j];
                int p = g_blockbase[blk * 64 + e] + g_loc[t * 3 + j];
                g_entry_token[p] = t;
                g_pos[t * 3 + j] = p;
            }
        }
    }

    grid_sync();

    // ================= Phase D: TF32 grouped GEMM, 64x128 tiles ================
    {
        float* As = sm;                  // [64][K4_LD]
        float* Bs = sm + 64 * K4_LD;     // [128][K4_LD]
        uint32_t bsb = (uint32_t)__cvta_generic_to_shared(Bs);
        int ntiles = g_ntiles;
        const float4* x4 = (const float4*)x;

        for (int t = cta; t < ntiles; t += GRID) {
            int2 tl = g_tiles[t];
            int e = tl.x, rs = tl.y;
            int rows = g_offsets[e + 1] - rs;
            if (rows > 64) rows = 64;

            __syncthreads();   // prior smem readers done

            // B: cp.async copy of pre-rounded W^T (4096 float4)
            const float4* wt4 = (const float4*)(g_wt + (size_t)e * DD * DD);
#pragma unroll
            for (int i = 0; i < 8; i++) {
                int idx = i * NT + tid;
                int o = idx >> 5, kq = idx & 31;
                cp_async16(bsb + (o * K4_LD + kq * 4) * 4, wt4 + idx);
            }
            CP_COMMIT();

            // A: gather + tf32 round + STS (8 threads per row)
            {
                int tr = tid >> 3, h = tid & 7;
                bool valid = tr < rows;
                int tok = valid ? g_entry_token[rs + tr] : 0;
                const float4* xr = x4 + (size_t)tok * 32;
#pragma unroll
                for (int i = 0; i < 4; i++) {
                    int kc = h * 4 + i;
                    float4 v = make_float4(0.f, 0.f, 0.f, 0.f);
                    if (valid) v = __ldg(xr + kc);
                    v.x = to_tf32(v.x); v.y = to_tf32(v.y);
                    v.z = to_tf32(v.z); v.w = to_tf32(v.w);
                    *(float4*)(As + tr * K4_LD + kc * 4) = v;
                }
            }
            CP_WAIT0();
            __syncthreads();

            int wid = tid >> 5, lane = tid & 31;
            int gid = lane >> 2, tig = lane & 3;
            int m0 = (wid & 3) * 16, n0 = (wid >> 2) * 32;

            float acc[4][4];
#pragma unroll
            for (int j = 0; j < 4; j++)
#pragma unroll
                for (int r = 0; r < 4; r++) acc[j][r] = 0.f;

            const float* arow = As + (m0 + gid) * K4_LD + tig;
            const float* brow = Bs + (n0 + gid) * K4_LD + tig;

#pragma unroll 4
            for (int kb = 0; kb < 128; kb += 8) {
                uint32_t a[4];
                {
                    const float* p = arow + kb;
                    a[0] = __float_as_uint(p[0]);
                    a[1] = __float_as_uint(p[8 * K4_LD]);
                    a[2] = __float_as_uint(p[4]);
                    a[3] = __float_as_uint(p[8 * K4_LD + 4]);
                }
                uint32_t b[4][2];
#pragma unroll
                for (int j = 0; j < 4; j++) {
                    const float* p = brow + j * 8 * K4_LD + kb;
                    b[j][0] = __float_as_uint(p[0]);
                    b[j][1] = __float_as_uint(p[4]);
                }
#pragma unroll
                for (int j = 0; j < 4; j++)
                    mma_tf32(acc[j], a, b[j]);
            }

            const float* be = bias + (size_t)e * DD;
            {
                int r0 = m0 + gid;
                int r1 = r0 + 8;
                bool v0 = r0 < rows, v1 = r1 < rows;
                float* o0 = g_scratch + (size_t)(rs + r0) * DD;
                float* o1 = g_scratch + (size_t)(rs + r1) * DD;
#pragma unroll
                for (int j = 0; j < 4; j++) {
                    int col = n0 + j * 8 + tig * 2;
                    float2 bv = *(const float2*)(be + col);
                    if (v0) *(float2*)(o0 + col) =
                        make_float2(acc[j][0] + bv.x, acc[j][1] + bv.y);
                    if (v1) *(float2*)(o1 + col) =
                        make_float2(acc[j][2] + bv.x, acc[j][3] + bv.y);
                }
            }
        }
    }

    grid_sync();

    // ================= Phase E: weighted combine ===============================
    {
        int gw = (cta * NT + tid) >> 5;        // global warp id, 0..4735
        int c = (tid & 31) * 4;
        for (int b = gw; b < BB; b += GRID * 16) {
            float4 r = make_float4(0.f, 0.f, 0.f, 0.f);
#pragma unroll
            for (int j = 0; j < 3; j++) {
                float w = g_w[b * 3 + j];
                int   p = g_pos[b * 3 + j];
                float4 sv = *(const float4*)(g_scratch + (size_t)p * DD + c);
                r.x += w * sv.x;
                r.y += w * sv.y;
                r.z += w * sv.z;
                r.w += w * sv.w;
            }
            *(float4*)(out + (size_t)b * DD + c) = r;
        }
    }
}

// ---------------- launch ------------------------------------------------------
extern "C" void kernel_launch(void* const* d_in, const int* in_sizes, int n_in,
                              void* d_out, int out_size) {
    const float* x    = (const float*)d_in[0];
    const float* dsc  = (const float*)d_in[1];
    const float* cent = (const float*)d_in[2];
    const float* W    = (const float*)d_in[3];
    const float* bias = (const float*)d_in[4];
    float* out = (float*)d_out;

    cudaFuncSetAttribute(fused, cudaFuncAttributeMaxDynamicSharedMemorySize,
                         FUSED_SMEM);
    fused<<<GRID, NT, FUSED_SMEM>>>(x, dsc, cent, W, bias, out);
}

// round 14
// speedup vs baseline: 1.4927x; 1.1215x over previous
#include <cuda_runtime.h>
#include <cstdint>

#define BB 16384
#define EE 64
#define DD 128
#define ES 3
#define NBLK (BB / 64)          // 256 route blocks
#define GRID 296                // 2 CTAs/SM x 148 SMs, all co-resident
#define NT 512
#define NTASK_A (NBLK + EE)     // 256 route + 64 wt tasks
#define ECHUNK 4
#define NTASK_E (BB / ECHUNK)

typedef unsigned long long ull;
typedef long long ll;

// ---------------- device scratch (static; no allocations allowed) -------------
__device__ int    g_offsets[EE + 1];
__device__ int    g_ntiles;
__device__ int    g_picked[BB * ES];
__device__ int    g_loc[BB * ES];
__device__ float  g_w[BB * ES];
__device__ int    g_entry_token[BB * ES];
__device__ int    g_pos[BB * ES];
__device__ int2   g_tiles[1024];
__device__ int    g_blockhist[NBLK * EE];
__device__ int    g_blockbase[NBLK * EE];
__device__ float  g_wt[(size_t)EE * DD * DD];        // tf32-rounded W^T [e][o][k]
__device__ float  g_scratch[(size_t)BB * ES * DD];   // 25 MB

// work-stealing counters (reset at end of every launch -> replay-safe)
__device__ int g_task_a = 0;
__device__ int g_task_d = 0;
__device__ int g_task_e = 0;

// ---------------- grid barrier (sense-reversing, replay-safe) ------------------
__device__ int          g_bar_count = 0;
__device__ volatile int g_bar_gen   = 0;

__device__ __forceinline__ void grid_sync() {
    __syncthreads();
    if (threadIdx.x == 0) {
        __threadfence();
        int gen = g_bar_gen;
        if (atomicAdd(&g_bar_count, 1) == GRID - 1) {
            g_bar_count = 0;
            __threadfence();
            g_bar_gen = gen + 1;
        } else {
            while (g_bar_gen == gen) __nanosleep(32);
        }
        __threadfence();
    }
    __syncthreads();
}

// ---------------- helpers ------------------------------------------------------
__device__ __forceinline__ ull pack2(float lo, float hi) {
    ull r;
    asm("mov.b64 %0, {%1, %2};" : "=l"(r) : "f"(lo), "f"(hi));
    return r;
}
__device__ __forceinline__ float2 unpack2(ull v) {
    float2 f;
    asm("mov.b64 {%0, %1}, %2;" : "=f"(f.x), "=f"(f.y) : "l"(v));
    return f;
}
__device__ __forceinline__ ull fma2(ull a, ull b, ull c) {
    ull d;
    asm("fma.rn.f32x2 %0, %1, %2, %3;" : "=l"(d) : "l"(a), "l"(b), "l"(c));
    return d;
}
__device__ __forceinline__ ull add2(ull a, ull b) {
    ull d;
    asm("add.rn.f32x2 %0, %1, %2;" : "=l"(d) : "l"(a), "l"(b));
    return d;
}
__device__ __forceinline__ float to_tf32(float x) {
    float r;
    asm("cvt.rna.tf32.f32 %0, %1;" : "=f"(r) : "f"(x));
    return r;
}
__device__ __forceinline__ void mma_tf32(float* c, const uint32_t* a,
                                         const uint32_t* b) {
    asm volatile(
        "mma.sync.aligned.m16n8k8.row.col.f32.tf32.tf32.f32 "
        "{%0,%1,%2,%3}, {%4,%5,%6,%7}, {%8,%9}, {%0,%1,%2,%3};"
        : "+f"(c[0]), "+f"(c[1]), "+f"(c[2]), "+f"(c[3])
        : "r"(a[0]), "r"(a[1]), "r"(a[2]), "r"(a[3]), "r"(b[0]), "r"(b[1]));
}
__device__ __forceinline__ void cp_async16(uint32_t dst, const void* src) {
    asm volatile("cp.async.cg.shared.global [%0], [%1], 16;"
                 :: "r"(dst), "l"(src) : "memory");
}
#define CP_COMMIT() asm volatile("cp.async.commit_group;" ::: "memory")
#define CP_WAIT0()  asm volatile("cp.async.wait_group 0;" ::: "memory")

// smem layout sizes
#define K1_XP 68
#define K1_CP 36
#define K1_TP 36
#define K4_LD 132
// GEMM: A[64][132] + B[128][132] = 101376 B (dominates routing's ~64KB)
#define FUSED_SMEM ((64 * K4_LD + 128 * K4_LD) * 4 + 128)

// ---------------- fused persistent kernel --------------------------------------
__global__ __launch_bounds__(NT, 2) void fused(const float* __restrict__ x,
                                               const float* __restrict__ dscale,
                                               const float* __restrict__ cent,
                                               const float* __restrict__ W,
                                               const float* __restrict__ bias,
                                               float* __restrict__ out) {
    extern __shared__ float sm[];
    __shared__ int s_task;
    int tid = threadIdx.x;
    int cta = blockIdx.x;

    // ================= Phase A: work-stealing over {route blocks, W^T} =========
    {
        float*  xs   = sm;                          // [128][K1_XP]
        float*  cs   = xs + 128 * K1_XP;            // [128][K1_CP]
        float*  ts   = cs + 128 * K1_CP;            // [64][K1_TP]
        double* nc2s = (double*)(ts + 64 * K1_TP);  // [32]
        int*    hist = (int*)(nc2s + 32);           // [64]
        double* nx2s = (double*)(hist + 64);        // [64]
        const float4* x4 = (const float4*)x;
        const float4* c4 = (const float4*)cent;

        for (;;) {
            if (tid == 0) s_task = atomicAdd(&g_task_a, 1);
            __syncthreads();
            int task = s_task;
            __syncthreads();
            if (task >= NTASK_A) break;

            if (task < NBLK) {
                // -------- route block --------
                int t0 = task * 64;
                if (tid < 64) hist[tid] = 0;
#pragma unroll
                for (int i = 0; i < 4; i++) {
                    int f = i * NT + tid;
                    int tr = f & 63, kc = f >> 6;
                    float4 v = __ldg(x4 + (size_t)(t0 + tr) * 32 + kc);
                    xs[(kc * 4 + 0) * K1_XP + tr] = v.x;
                    xs[(kc * 4 + 1) * K1_XP + tr] = v.y;
                    xs[(kc * 4 + 2) * K1_XP + tr] = v.z;
                    xs[(kc * 4 + 3) * K1_XP + tr] = v.w;
                }
#pragma unroll
                for (int i = 0; i < 2; i++) {
                    int f = i * NT + tid;
                    int er = f & 31, kc = f >> 5;
                    float4 v = __ldg(c4 + (size_t)er * 32 + kc);
                    cs[(kc * 4 + 0) * K1_CP + er] = v.x;
                    cs[(kc * 4 + 1) * K1_CP + er] = v.y;
                    cs[(kc * 4 + 2) * K1_CP + er] = v.z;
                    cs[(kc * 4 + 3) * K1_CP + er] = v.w;
                }
                __syncthreads();

                if (tid < 32) {
                    double a0 = 0.0, a1 = 0.0;
#pragma unroll 8
                    for (int k = 0; k < 128; k += 2) {
                        double u0 = (double)cs[(k + 0) * K1_CP + tid]; a0 = fma(u0, u0, a0);
                        double u1 = (double)cs[(k + 1) * K1_CP + tid]; a1 = fma(u1, u1, a1);
                    }
                    nc2s[tid] = a0 + a1;
                }

                // |x|^2, one thread per token (value bit-identical to before)
                if (tid >= 64 && tid < 128) {
                    int tok = tid - 64;
                    double a0 = 0.0, a1 = 0.0, a2 = 0.0, a3 = 0.0;
#pragma unroll 8
                    for (int k = 0; k < 128; k += 4) {
                        double u0 = (double)xs[(k + 0) * K1_XP + tok]; a0 = fma(u0, u0, a0);
                        double u1 = (double)xs[(k + 1) * K1_XP + tok]; a1 = fma(u1, u1, a1);
                        double u2 = (double)xs[(k + 2) * K1_XP + tok]; a2 = fma(u2, u2, a2);
                        double u3 = (double)xs[(k + 3) * K1_XP + tok]; a3 = fma(u3, u3, a3);
                    }
                    nx2s[tok] = (a0 + a1) + (a2 + a3);
                }

                // dots (unchanged mapping, threads 0..255)
                if (tid < 256) {
                    int tx = tid & 7, ty = tid >> 3;
                    ull acc[2][2][4];
#pragma unroll
                    for (int i = 0; i < 2; i++)
#pragma unroll
                        for (int j = 0; j < 2; j++)
#pragma unroll
                            for (int s = 0; s < 4; s++) acc[i][j][s] = 0ULL;

                    const float* ap = xs + ty * 2;
                    const float* bp = cs + tx * 4;
#pragma unroll 4
                    for (int k = 0; k < 128; k += 4) {
#pragma unroll
                        for (int s = 0; s < 4; s++) {
                            float2  a  = *(const float2*)(ap + (k + s) * K1_XP);
                            double2 nb = *(const double2*)(bp + (k + s) * K1_CP);
                            ull b01 = __double_as_longlong(nb.x);
                            ull b23 = __double_as_longlong(nb.y);
                            ull a0 = pack2(a.x, a.x), a1 = pack2(a.y, a.y);
                            acc[0][0][s] = fma2(a0, b01, acc[0][0][s]);
                            acc[0][1][s] = fma2(a0, b23, acc[0][1][s]);
                            acc[1][0][s] = fma2(a1, b01, acc[1][0][s]);
                            acc[1][1][s] = fma2(a1, b23, acc[1][1][s]);
                        }
                    }
#pragma unroll
                    for (int i = 0; i < 2; i++) {
                        ull s01 = add2(add2(acc[i][0][0], acc[i][0][1]),
                                       add2(acc[i][0][2], acc[i][0][3]));
                        ull s23 = add2(add2(acc[i][1][0], acc[i][1][1]),
                                       add2(acc[i][1][2], acc[i][1][3]));
                        float2 v01 = unpack2(s01), v23 = unpack2(s23);
                        int tok = ty * 2 + i;
                        *(float4*)(ts + tok * K1_TP + tx * 4) =
                            make_float4(v01.x, v01.y, v23.x, v23.y);
                    }
                }
                __syncthreads();

                // ranking: 2 threads/token, int64 compares (order-isomorphic,
                // distances are strictly positive at this scale)
                if (tid < 128) {
                    int tok = tid >> 1, side = tid & 1;
                    double nx2 = nx2s[tok];
                    float  s  = __ldg(dscale);
                    double Kd = ((double)s * (double)s) * (1.0 / 128.0);

                    ll av[3] = {0x7FF0000000000000LL, 0x7FF0000000000000LL,
                                0x7FF0000000000000LL};
                    int ai[3] = {0, 0, 0};
                    for (int ei = 0; ei < 32; ei++) {
                        double t  = (double)ts[tok * K1_TP + ei];
                        double br = nx2 + nc2s[ei];
                        double dd = Kd * (side == 0 ? fma(-2.0, t, br)
                                                    : fma(2.0, t, br));
                        ll db = __double_as_longlong(dd);
                        int e = side * 32 + ei;
                        if (db < av[0]) {
                            av[2] = av[1]; ai[2] = ai[1];
                            av[1] = av[0]; ai[1] = ai[0];
                            av[0] = db;    ai[0] = e;
                        } else if (db < av[1]) {
                            av[2] = av[1]; ai[2] = ai[1];
                            av[1] = db;    ai[1] = e;
                        } else if (db < av[2]) {
                            av[2] = db;    ai[2] = e;
                        }
                    }
                    ll  bv[3];
                    int bi[3];
#pragma unroll
                    for (int r = 0; r < 3; r++) {
                        bv[r] = __shfl_down_sync(0xFFFFFFFFu, av[r], 1);
                        bi[r] = __shfl_down_sync(0xFFFFFFFFu, ai[r], 1);
                    }
                    if (side == 0) {
                        int ri[3]; int pa = 0, pb = 0;
#pragma unroll
                        for (int r = 0; r < 3; r++) {
                            bool takeB = (pa > 2) || (pb <= 2 && bv[pb] < av[pa]);
                            if (takeB) { ri[r] = bi[pb]; pb++; }
                            else       { ri[r] = ai[pa]; pa++; }
                        }
                        float d0 = (float)(Kd * fma(-2.0, (double)ts[tok * K1_TP + 0], nx2 + nc2s[0]));
                        float d1 = (float)(Kd * fma(-2.0, (double)ts[tok * K1_TP + 1], nx2 + nc2s[1]));
                        float d2 = (float)(Kd * fma(-2.0, (double)ts[tok * K1_TP + 2], nx2 + nc2s[2]));
                        float w0 = 1.0f / (1.0f + d0);
                        float w1 = 1.0f / (1.0f + d1);
                        float w2 = 1.0f / (1.0f + d2);
                        float z  = w0 + w1 + w2;
                        int b = t0 + tok;
                        g_picked[b * 3 + 0] = ri[0];
                        g_picked[b * 3 + 1] = ri[1];
                        g_picked[b * 3 + 2] = ri[2];
                        g_w[b * 3 + 0] = w0 / z;
                        g_w[b * 3 + 1] = w1 / z;
                        g_w[b * 3 + 2] = w2 / z;
                        g_loc[b * 3 + 0] = atomicAdd(&hist[ri[0]], 1);
                        g_loc[b * 3 + 1] = atomicAdd(&hist[ri[1]], 1);
                        g_loc[b * 3 + 2] = atomicAdd(&hist[ri[2]], 1);
                    }
                }
                __syncthreads();
                if (tid < 64) g_blockhist[task * 64 + tid] = hist[tid];
                __syncthreads();
            } else {
                // -------- W^T build for expert e --------
                int e = task - NBLK;
                float* wsm = sm;                     // [128][132] wsm[k][o]
                const float4* w4 = (const float4*)(W + (size_t)e * DD * DD);
#pragma unroll
                for (int i = 0; i < 8; i++) {
                    int idx = i * NT + tid;
                    float4 v = __ldg(w4 + idx);
                    *(float4*)(wsm + (idx >> 5) * 132 + (idx & 31) * 4) = v;
                }
                __syncthreads();
                float4* dst = (float4*)(g_wt + (size_t)e * DD * DD);
#pragma unroll
                for (int i = 0; i < 8; i++) {
                    int idx = i * NT + tid;
                    int o = idx >> 5, kq = idx & 31;
                    float4 v;
                    v.x = to_tf32(wsm[(kq * 4 + 0) * 132 + o]);
                    v.y = to_tf32(wsm[(kq * 4 + 1) * 132 + o]);
                    v.z = to_tf32(wsm[(kq * 4 + 2) * 132 + o]);
                    v.w = to_tf32(wsm[(kq * 4 + 3) * 132 + o]);
                    dst[o * 32 + kq] = v;
                }
                __syncthreads();
            }
        }
    }

    grid_sync();

    // ================= Phase B: scan (CTA 0) ===================================
    if (cta == 0) {
        int* csum = (int*)sm;        // [256]
        int* cnts = csum + 256;      // [64]
        int* off  = cnts + 64;       // [65]
        int* toff = off + 65;        // [64]
        int e = tid & 63, c = (tid >> 6) & 3;

        if (tid < 256) {
            int s = 0;
#pragma unroll 8
            for (int i = 0; i < 64; i++) s += g_blockhist[((c << 6) + i) * 64 + e];
            csum[c * 64 + e] = s;
        }
        __syncthreads();

        if (tid < 64) {
            int t0 = csum[0 * 64 + tid], t1 = csum[1 * 64 + tid];
            int t2 = csum[2 * 64 + tid], t3 = csum[3 * 64 + tid];
            cnts[tid] = t0 + t1 + t2 + t3;
            csum[0 * 64 + tid] = 0;
            csum[1 * 64 + tid] = t0;
            csum[2 * 64 + tid] = t0 + t1;
            csum[3 * 64 + tid] = t0 + t1 + t2;
        }
        __syncthreads();

        if (tid == 0) {
            int o = 0, to = 0;
            for (int i = 0; i < 64; i++) {
                off[i] = o; toff[i] = to;
                o += cnts[i]; to += (cnts[i] + 63) >> 6;
            }
            off[64] = o; g_ntiles = to;
        }
        __syncthreads();

        if (tid < 64) {
            g_offsets[tid] = off[tid];
            int nt = (cnts[tid] + 63) >> 6;
            for (int i = 0; i < nt; i++)
                g_tiles[toff[tid] + i] = make_int2(tid, off[tid] + (i << 6));
        }
        if (tid == 0) g_offsets[64] = off[64];
        __syncthreads();

        if (tid < 256) {
            int run = off[e] + csum[c * 64 + e];
            for (int i = 0; i < 64; i++) {
                int idx = ((c << 6) + i) * 64 + e;
                int v = g_blockhist[idx];
                g_blockbase[idx] = run;
                run += v;
            }
        }
    }

    grid_sync();

    // ================= Phase C: scatter ========================================
    {
        int t = cta * NT + tid;
        if (t < BB) {
            int blk = t >> 6;
#pragma unroll
            for (int j = 0; j < 3; j++) {
                int e = g_picked[t * 3 + j];
                int p = g_blockbase[blk * 64 + e] + g_loc[t * 3 + j];
                g_entry_token[p] = t;
                g_pos[t * 3 + j] = p;
            }
        }
    }

    grid_sync();

    // ================= Phase D: TF32 grouped GEMM, work-stealing ===============
    {
        float* As = sm;                  // [64][K4_LD]
        float* Bs = sm + 64 * K4_LD;     // [128][K4_LD]
        uint32_t bsb = (uint32_t)__cvta_generic_to_shared(Bs);
        int ntiles = g_ntiles;
        const float4* x4 = (const float4*)x;

        for (;;) {
            if (tid == 0) s_task = atomicAdd(&g_task_d, 1);
            __syncthreads();
            int t = s_task;
            __syncthreads();
            if (t >= ntiles) break;

            int2 tl = g_tiles[t];
            int e = tl.x, rs = tl.y;
            int rows = g_offsets[e + 1] - rs;
            if (rows > 64) rows = 64;

            // B: cp.async copy of pre-rounded W^T (4096 float4)
            const float4* wt4 = (const float4*)(g_wt + (size_t)e * DD * DD);
#pragma unroll
            for (int i = 0; i < 8; i++) {
                int idx = i * NT + tid;
                int o = idx >> 5, kq = idx & 31;
                cp_async16(bsb + (o * K4_LD + kq * 4) * 4, wt4 + idx);
            }
            CP_COMMIT();

            // A: gather + tf32 round + STS (8 threads per row)
            {
                int tr = tid >> 3, h = tid & 7;
                bool valid = tr < rows;
                int tok = valid ? g_entry_token[rs + tr] : 0;
                const float4* xr = x4 + (size_t)tok * 32;
#pragma unroll
                for (int i = 0; i < 4; i++) {
                    int kc = h * 4 + i;
                    float4 v = make_float4(0.f, 0.f, 0.f, 0.f);
                    if (valid) v = __ldg(xr + kc);
                    v.x = to_tf32(v.x); v.y = to_tf32(v.y);
                    v.z = to_tf32(v.z); v.w = to_tf32(v.w);
                    *(float4*)(As + tr * K4_LD + kc * 4) = v;
                }
            }
            CP_WAIT0();
            __syncthreads();

            int wid = tid >> 5, lane = tid & 31;
            int gid = lane >> 2, tig = lane & 3;
            int m0 = (wid & 3) * 16, n0 = (wid >> 2) * 32;

            float acc[4][4];
#pragma unroll
            for (int j = 0; j < 4; j++)
#pragma unroll
                for (int r = 0; r < 4; r++) acc[j][r] = 0.f;

            const float* arow = As + (m0 + gid) * K4_LD + tig;
            const float* brow = Bs + (n0 + gid) * K4_LD + tig;

#pragma unroll 4
            for (int kb = 0; kb < 128; kb += 8) {
                uint32_t a[4];
                {
                    const float* p = arow + kb;
                    a[0] = __float_as_uint(p[0]);
                    a[1] = __float_as_uint(p[8 * K4_LD]);
                    a[2] = __float_as_uint(p[4]);
                    a[3] = __float_as_uint(p[8 * K4_LD + 4]);
                }
                uint32_t b[4][2];
#pragma unroll
                for (int j = 0; j < 4; j++) {
                    const float* p = brow + j * 8 * K4_LD + kb;
                    b[j][0] = __float_as_uint(p[0]);
                    b[j][1] = __float_as_uint(p[4]);
                }
#pragma unroll
                for (int j = 0; j < 4; j++)
                    mma_tf32(acc[j], a, b[j]);
            }

            const float* be = bias + (size_t)e * DD;
            {
                int r0 = m0 + gid;
                int r1 = r0 + 8;
                bool v0 = r0 < rows, v1 = r1 < rows;
                float* o0 = g_scratch + (size_t)(rs + r0) * DD;
                float* o1 = g_scratch + (size_t)(rs + r1) * DD;
#pragma unroll
                for (int j = 0; j < 4; j++) {
                    int col = n0 + j * 8 + tig * 2;
                    float2 bv = *(const float2*)(be + col);
                    if (v0) *(float2*)(o0 + col) =
                        make_float2(acc[j][0] + bv.x, acc[j][1] + bv.y);
                    if (v1) *(float2*)(o1 + col) =
                        make_float2(acc[j][2] + bv.x, acc[j][3] + bv.y);
                }
            }
        }
    }

    grid_sync();

    // ================= Phase E: weighted combine, per-warp stealing ============
    {
        int lane = tid & 31;
        int c = lane * 4;
        for (;;) {
            int ch;
            if (lane == 0) ch = atomicAdd(&g_task_e, 1);
            ch = __shfl_sync(0xFFFFFFFFu, ch, 0);
            if (ch >= NTASK_E) break;
            int b0 = ch * ECHUNK;
#pragma unroll
            for (int b = b0; b < b0 + ECHUNK; b++) {
                float4 r = make_float4(0.f, 0.f, 0.f, 0.f);
#pragma unroll
                for (int j = 0; j < 3; j++) {
                    float w = g_w[b * 3 + j];
                    int   p = g_pos[b * 3 + j];
                    float4 sv = *(const float4*)(g_scratch + (size_t)p * DD + c);
                    r.x += w * sv.x;
                    r.y += w * sv.y;
                    r.z += w * sv.z;
                    r.w += w * sv.w;
                }
                *(float4*)(out + (size_t)b * DD + c) = r;
            }
        }
    }

    grid_sync();   // all stealing done -> safe to reset counters for next replay
    if (cta == 0 && tid == 0) {
        g_task_a = 0;
        g_task_d = 0;
        g_task_e = 0;
    }
}

// ---------------- launch ------------------------------------------------------
extern "C" void kernel_launch(void* const* d_in, const int* in_sizes, int n_in,
                              void* d_out, int out_size) {
    const float* x    = (const float*)d_in[0];
    const float* dsc  = (const float*)d_in[1];
    const float* cent = (const float*)d_in[2];
    const float* W    = (const float*)d_in[3];
    const float* bias = (const float*)d_in[4];
    float* out = (float*)d_out;

    cudaFuncSetAttribute(fused, cudaFuncAttributeMaxDynamicSharedMemorySize,
                         FUSED_SMEM);
    fused<<<GRID, NT, FUSED_SMEM>>>(x, dsc, cent, W, bias, out);
}